// round 1
// baseline (speedup 1.0000x reference)
#include <cuda_runtime.h>
#include <cuda_bf16.h>
#include <cstdint>

typedef unsigned long long ull;

// ---------------------------------------------------------------------------
// Problem constants: B=4, C=64, H=W=64, N=4096
// ---------------------------------------------------------------------------
#define BATCH 4
#define CH    64
#define HW    64
#define NPIX  4096              // 64*64
#define EPSBN 1e-5f

// ---------------------------------------------------------------------------
// Scratch (static device memory — no allocations anywhere)
// ---------------------------------------------------------------------------
__device__ float g_c1raw[BATCH * CH * NPIX];   // conv output before BN (reused)
__device__ float g_x1   [BATCH * CH * NPIX];
__device__ float g_theta[BATCH * CH * NPIX];
__device__ float g_phi  [BATCH * CH * NPIX];
__device__ float g_gm   [BATCH * CH * NPIX];
__device__ float g_y    [BATCH * CH * NPIX];
__device__ float g_z    [BATCH * CH * NPIX];
__device__ float g_f    [(size_t)BATCH * NPIX * NPIX];   // 268 MB logits
__device__ float g_rowmax[BATCH * NPIX];
__device__ float g_rowsum[BATCH * NPIX];
__device__ float g_mean[CH];
__device__ float g_rstd[CH];
__device__ float g_wT[5 * 3 * CH * 3 * CH];    // 5 transposed 3x3 weight sets

// ---------------------------------------------------------------------------
// f32x2 packed-FMA helpers (Blackwell FFMA2 — only reachable via PTX)
// ---------------------------------------------------------------------------
__device__ __forceinline__ ull pk2(float lo, float hi) {
    ull r; asm("mov.b64 %0, {%1, %2};" : "=l"(r) : "f"(lo), "f"(hi)); return r;
}
__device__ __forceinline__ void fma2(ull& d, ull a, ull b) {
    asm("fma.rn.f32x2 %0, %1, %2, %0;" : "+l"(d) : "l"(a), "l"(b));
}
__device__ __forceinline__ float2 upk2(ull v) {
    float2 r; asm("mov.b64 {%0, %1}, %2;" : "=f"(r.x), "=f"(r.y) : "l"(v)); return r;
}

// ---------------------------------------------------------------------------
// Weight transpose: w[co][ci][kh][kw]  ->  wT[kh][ci][kw][co]
// ---------------------------------------------------------------------------
__global__ void wtrans_kernel(const float* __restrict__ w, float* __restrict__ wT) {
    int i = blockIdx.x * 256 + threadIdx.x;
    if (i < CH * CH * 9) {
        int kw = i % 3, kh = (i / 3) % 3, ci = (i / 9) % CH, co = i / (9 * CH);
        wT[((kh * CH + ci) * 3 + kw) * CH + co] = w[i];
    }
}

// ---------------------------------------------------------------------------
// Direct 3x3 conv, pad=1. One block = one (b, h) row, all 64 output channels,
// all 64 pixels of the row. dyn smem: sRow[64ci][66] + sW[ci][kw][co] (12288).
// Thread (cg = tid>>4, pg = tid&15): co = cg*4+i (i<4), pixels w = pg*2 + jp*32 + k.
// ---------------------------------------------------------------------------
__global__ void __launch_bounds__(256) conv3x3_kernel(
    const float* __restrict__ in, const float* __restrict__ wT,
    const float* __restrict__ bias, float* __restrict__ out)
{
    extern __shared__ float smem[];
    float* sRow = smem;              // 64*66 = 4224 floats
    float* sW   = smem + 64 * 66;    // 12288 floats: [ci][kw][co]

    const int b   = blockIdx.x >> 6;
    const int h   = blockIdx.x & 63;
    const int tid = threadIdx.x;
    const int cg  = tid >> 4;
    const int pg  = tid & 15;

    ull acc[4][2];
    #pragma unroll
    for (int i = 0; i < 4; ++i) { acc[i][0] = 0ull; acc[i][1] = 0ull; }

    for (int kh = 0; kh < 3; ++kh) {
        const int row = h + kh - 1;
        // weights slice for this kh (contiguous, pre-transposed)
        const float* wsrc = wT + kh * (CH * 3 * CH);
        for (int i = tid; i < CH * 3 * CH; i += 256) sW[i] = wsrc[i];
        // input row (zero-padded left/right, zero if row out of range)
        if (row >= 0 && row < HW) {
            const float* src = in + (size_t)(b * CH) * NPIX + row * HW;
            for (int i = tid; i < CH * HW; i += 256) {
                int ci = i >> 6, w = i & 63;
                sRow[ci * 66 + 1 + w] = src[(size_t)ci * NPIX + w];
            }
        } else {
            for (int i = tid; i < CH * HW; i += 256) {
                int ci = i >> 6, w = i & 63;
                sRow[ci * 66 + 1 + w] = 0.f;
            }
        }
        if (tid < 64) { sRow[tid * 66] = 0.f; sRow[tid * 66 + 65] = 0.f; }
        __syncthreads();

        #pragma unroll 4
        for (int ci = 0; ci < CH; ++ci) {
            const int rb = ci * 66 + (pg << 1);
            // 4 consecutive input cols per jp cover (k,kw) pairs
            float2 A01 = *(const float2*)&sRow[rb];
            float2 A23 = *(const float2*)&sRow[rb + 2];
            float2 B01 = *(const float2*)&sRow[rb + 32];
            float2 B23 = *(const float2*)&sRow[rb + 34];
            ull pA[3], pB[3];
            pA[0] = pk2(A01.x, A01.y); pA[1] = pk2(A01.y, A23.x); pA[2] = pk2(A23.x, A23.y);
            pB[0] = pk2(B01.x, B01.y); pB[1] = pk2(B01.y, B23.x); pB[2] = pk2(B23.x, B23.y);
            const float* wp = &sW[ci * 192 + (cg << 2)];
            #pragma unroll
            for (int kw = 0; kw < 3; ++kw) {
                float4 wv = *(const float4*)(wp + kw * 64);
                const float wf[4] = {wv.x, wv.y, wv.z, wv.w};
                #pragma unroll
                for (int i = 0; i < 4; ++i) {
                    ull wd = pk2(wf[i], wf[i]);
                    fma2(acc[i][0], wd, pA[kw]);
                    fma2(acc[i][1], wd, pB[kw]);
                }
            }
        }
        __syncthreads();
    }

    const int w0 = pg << 1;
    #pragma unroll
    for (int i = 0; i < 4; ++i) {
        int co = (cg << 2) + i;
        float bv = bias ? bias[co] : 0.f;
        float2 r0 = upk2(acc[i][0]);
        float2 r1 = upk2(acc[i][1]);
        r0.x += bv; r0.y += bv; r1.x += bv; r1.y += bv;
        float* o = out + (size_t)(b * CH + co) * NPIX + h * HW;
        *(float2*)&o[w0]      = r0;
        *(float2*)&o[w0 + 32] = r1;
    }
}

// ---------------------------------------------------------------------------
// BN stats (training-mode, biased variance) — one block per channel
// ---------------------------------------------------------------------------
__global__ void __launch_bounds__(256) bnstats_kernel(
    const float* __restrict__ v, float* __restrict__ mean, float* __restrict__ rstd)
{
    const int c = blockIdx.x;
    const int tid = threadIdx.x;
    float s = 0.f, s2 = 0.f;
    for (int i = tid; i < BATCH * NPIX; i += 256) {
        int b = i >> 12, p = i & 4095;
        float x = v[(size_t)(b * CH + c) * NPIX + p];
        s += x; s2 += x * x;
    }
    #pragma unroll
    for (int off = 16; off; off >>= 1) {
        s  += __shfl_xor_sync(0xffffffffu, s,  off);
        s2 += __shfl_xor_sync(0xffffffffu, s2, off);
    }
    __shared__ float ws[8], ws2[8];
    if ((tid & 31) == 0) { ws[tid >> 5] = s; ws2[tid >> 5] = s2; }
    __syncthreads();
    if (tid == 0) {
        float S = 0.f, S2 = 0.f;
        #pragma unroll
        for (int i = 0; i < 8; ++i) { S += ws[i]; S2 += ws2[i]; }
        float m = S * (1.f / (BATCH * NPIX));
        float var = S2 * (1.f / (BATCH * NPIX)) - m * m;
        mean[c] = m;
        rstd[c] = rsqrtf(var + EPSBN);
    }
}

// BN apply + ReLU (elementwise)
__global__ void __launch_bounds__(256) bnapply_kernel(
    const float* __restrict__ v, const float* __restrict__ mean,
    const float* __restrict__ rstd, const float* __restrict__ gamma,
    const float* __restrict__ beta, float* __restrict__ out)
{
    int i = blockIdx.x * 256 + threadIdx.x;
    int c = (i >> 12) & 63;
    float r = (v[i] - mean[c]) * rstd[c] * gamma[c] + beta[c];
    out[i] = fmaxf(r, 0.f);
}

// ---------------------------------------------------------------------------
// GEMM1: f[b][n][m] = sum_c theta[b][c][n] * phi[b][c][m]
// grid (64 m-tiles, 64 n-tiles, 4 b), 256 threads, 64x64 tile, K=64
// ---------------------------------------------------------------------------
__global__ void __launch_bounds__(256) gemm_qk_kernel(
    const float* __restrict__ theta, const float* __restrict__ phi,
    float* __restrict__ f)
{
    __shared__ float sA[64 * 64];   // theta tile [c][n]
    __shared__ float sB[64 * 64];   // phi tile   [c][m]
    const int m0 = blockIdx.x * 64, n0 = blockIdx.y * 64, b = blockIdx.z;
    const int tid = threadIdx.x, cg = tid >> 4, pg = tid & 15;

    const float* tp = theta + (size_t)b * CH * NPIX;
    const float* pp = phi   + (size_t)b * CH * NPIX;
    for (int i = tid; i < 64 * 64; i += 256) {
        int c = i >> 6, q = i & 63;
        sA[i] = tp[(size_t)c * NPIX + n0 + q];
        sB[i] = pp[(size_t)c * NPIX + m0 + q];
    }
    __syncthreads();

    ull acc[4][2];
    #pragma unroll
    for (int i = 0; i < 4; ++i) { acc[i][0] = 0ull; acc[i][1] = 0ull; }

    #pragma unroll 8
    for (int c = 0; c < 64; ++c) {
        const float* ar = &sA[c * 64];
        const float* br = &sB[c * 64];
        ull b0 = *(const ull*)&br[pg * 2];
        ull b1 = *(const ull*)&br[pg * 2 + 32];
        #pragma unroll
        for (int i = 0; i < 4; ++i) {
            float a = ar[cg + i * 16];
            ull ad = pk2(a, a);
            fma2(acc[i][0], ad, b0);
            fma2(acc[i][1], ad, b1);
        }
    }

    float* fb = f + ((size_t)b << 24) + (size_t)n0 * NPIX + m0;
    #pragma unroll
    for (int i = 0; i < 4; ++i) {
        int n = cg + i * 16;
        *(float2*)&fb[(size_t)n * NPIX + pg * 2]      = upk2(acc[i][0]);
        *(float2*)&fb[(size_t)n * NPIX + pg * 2 + 32] = upk2(acc[i][1]);
    }
}

// ---------------------------------------------------------------------------
// Row stats for softmax: max and sum(exp(v-max)) per row of f
// ---------------------------------------------------------------------------
__global__ void __launch_bounds__(128) rowstats_kernel(
    const float* __restrict__ f, float* __restrict__ rmax, float* __restrict__ rsum)
{
    const int r = blockIdx.x;                  // r = b*4096 + n
    const float* row = f + (size_t)r * NPIX;
    const int tid = threadIdx.x;
    float v[32];
    float mx = -1e30f;
    #pragma unroll
    for (int k = 0; k < 32; ++k) { v[k] = row[tid + (k << 7)]; mx = fmaxf(mx, v[k]); }
    #pragma unroll
    for (int off = 16; off; off >>= 1) mx = fmaxf(mx, __shfl_xor_sync(0xffffffffu, mx, off));
    __shared__ float sm[4];
    if ((tid & 31) == 0) sm[tid >> 5] = mx;
    __syncthreads();
    mx = fmaxf(fmaxf(sm[0], sm[1]), fmaxf(sm[2], sm[3]));
    float s = 0.f;
    #pragma unroll
    for (int k = 0; k < 32; ++k) s += __expf(v[k] - mx);
    #pragma unroll
    for (int off = 16; off; off >>= 1) s += __shfl_xor_sync(0xffffffffu, s, off);
    __shared__ float ss[4];
    if ((tid & 31) == 0) ss[tid >> 5] = s;
    __syncthreads();
    if (tid == 0) { rmax[r] = mx; rsum[r] = ss[0] + ss[1] + ss[2] + ss[3]; }
}

// ---------------------------------------------------------------------------
// GEMM2 (+softmax): y[b][c][n] = (1/rowsum[n]) * sum_m exp(f[n][m]-rowmax[n]) * g[b][c][m]
// grid (64 n-tiles, 4 b), 256 threads, output tile 64c x 64n, K=4096
// ---------------------------------------------------------------------------
__global__ void __launch_bounds__(256) gemm_pv_kernel(
    const float* __restrict__ f, const float* __restrict__ gm,
    const float* __restrict__ rowmax, const float* __restrict__ rowsum,
    float* __restrict__ y)
{
    __shared__ float sFt[64 * 66];  // exp'd f tile transposed: [m][n]
    __shared__ float sG[64 * 64];   // [c][m]
    __shared__ float sMax[64], sInv[64];

    const int n0 = blockIdx.x * 64, b = blockIdx.y;
    const int tid = threadIdx.x, cg = tid >> 4, pg = tid & 15;

    if (tid < 64) {
        int r = b * NPIX + n0 + tid;
        sMax[tid] = rowmax[r];
        sInv[tid] = 1.f / rowsum[r];
    }

    ull acc[4][2];
    #pragma unroll
    for (int i = 0; i < 4; ++i) { acc[i][0] = 0ull; acc[i][1] = 0ull; }

    const float* fb = f  + ((size_t)b << 24) + (size_t)n0 * NPIX;
    const float* gb = gm + (size_t)b * CH * NPIX;

    for (int m0 = 0; m0 < NPIX; m0 += 64) {
        __syncthreads();
        for (int i = tid; i < 64 * 64; i += 256) {
            int n = i >> 6, m = i & 63;
            float v = fb[(size_t)n * NPIX + m0 + m];
            sFt[m * 66 + n] = __expf(v - sMax[n]);
            sG[i] = gb[(size_t)(i >> 6) * NPIX + m0 + (i & 63)];
        }
        __syncthreads();
        #pragma unroll 8
        for (int m = 0; m < 64; ++m) {
            ull b0 = *(const ull*)&sFt[m * 66 + pg * 2];
            ull b1 = *(const ull*)&sFt[m * 66 + pg * 2 + 32];
            #pragma unroll
            for (int i = 0; i < 4; ++i) {
                float a = sG[(cg + i * 16) * 64 + m];
                ull ad = pk2(a, a);
                fma2(acc[i][0], ad, b0);
                fma2(acc[i][1], ad, b1);
            }
        }
    }

    #pragma unroll
    for (int i = 0; i < 4; ++i) {
        int c = cg + i * 16;
        float2 v0 = upk2(acc[i][0]);
        float2 v1 = upk2(acc[i][1]);
        v0.x *= sInv[pg * 2];      v0.y *= sInv[pg * 2 + 1];
        v1.x *= sInv[pg * 2 + 32]; v1.y *= sInv[pg * 2 + 33];
        float* yo = y + (size_t)(b * CH + c) * NPIX + n0;
        *(float2*)&yo[pg * 2]      = v0;
        *(float2*)&yo[pg * 2 + 32] = v1;
    }
}

// ---------------------------------------------------------------------------
// 1x1 W conv + bias + residual: z = Ww @ y + Wb + x  (per batch, per pixel)
// ---------------------------------------------------------------------------
__global__ void __launch_bounds__(64) wconv_kernel(
    const float* __restrict__ y, const float* __restrict__ Ww,
    const float* __restrict__ Wb, const float* __restrict__ x,
    float* __restrict__ z)
{
    __shared__ float sW[CH * CH];
    __shared__ float sB[CH];
    const int tid = threadIdx.x;
    for (int i = tid; i < CH * CH; i += 64) sW[i] = Ww[i];
    if (tid < CH) sB[tid] = Wb[tid];
    __syncthreads();

    const int pix = blockIdx.x * 64 + tid;
    const int b = pix >> 12, n = pix & 4095;

    float yv[CH];
    #pragma unroll
    for (int ci = 0; ci < CH; ++ci) yv[ci] = y[(size_t)(b * CH + ci) * NPIX + n];

    #pragma unroll 1
    for (int co = 0; co < CH; ++co) {
        float acc = sB[co];
        #pragma unroll
        for (int ci = 0; ci < CH; ++ci) acc += sW[co * CH + ci] * yv[ci];
        size_t o = (size_t)(b * CH + co) * NPIX + n;
        z[o] = acc + x[o];
    }
}

// ---------------------------------------------------------------------------
// Launch
// ---------------------------------------------------------------------------
extern "C" void kernel_launch(void* const* d_in, const int* in_sizes, int n_in,
                              void* d_out, int out_size)
{
    const float* x       = (const float*)d_in[0];
    const float* conv1_w = (const float*)d_in[1];
    const float* bn1_g   = (const float*)d_in[2];
    const float* bn1_b   = (const float*)d_in[3];
    const float* theta_w = (const float*)d_in[4];
    const float* theta_b = (const float*)d_in[5];
    const float* phi_w   = (const float*)d_in[6];
    const float* phi_b   = (const float*)d_in[7];
    const float* gw      = (const float*)d_in[8];
    const float* gb      = (const float*)d_in[9];
    const float* W_w     = (const float*)d_in[10];
    const float* W_b     = (const float*)d_in[11];
    const float* conv2_w = (const float*)d_in[12];
    const float* bn2_g   = (const float*)d_in[13];
    const float* bn2_b   = (const float*)d_in[14];
    float* out = (float*)d_out;

    float *p_c1, *p_x1, *p_th, *p_ph, *p_gm, *p_y, *p_z, *p_f, *p_rm, *p_rs, *p_mean, *p_rstd, *p_wT;
    cudaGetSymbolAddress((void**)&p_c1,  g_c1raw);
    cudaGetSymbolAddress((void**)&p_x1,  g_x1);
    cudaGetSymbolAddress((void**)&p_th,  g_theta);
    cudaGetSymbolAddress((void**)&p_ph,  g_phi);
    cudaGetSymbolAddress((void**)&p_gm,  g_gm);
    cudaGetSymbolAddress((void**)&p_y,   g_y);
    cudaGetSymbolAddress((void**)&p_z,   g_z);
    cudaGetSymbolAddress((void**)&p_f,   g_f);
    cudaGetSymbolAddress((void**)&p_rm,  g_rowmax);
    cudaGetSymbolAddress((void**)&p_rs,  g_rowsum);
    cudaGetSymbolAddress((void**)&p_mean, g_mean);
    cudaGetSymbolAddress((void**)&p_rstd, g_rstd);
    cudaGetSymbolAddress((void**)&p_wT,  g_wT);

    const int WSZ = 3 * CH * 3 * CH;      // 36864 per weight set
    const int CONV_SMEM = (64 * 66 + CH * 3 * CH) * (int)sizeof(float);  // 66048 B
    cudaFuncSetAttribute(conv3x3_kernel, cudaFuncAttributeMaxDynamicSharedMemorySize, CONV_SMEM);

    // transpose all five 3x3 weight tensors
    wtrans_kernel<<<144, 256>>>(conv1_w, p_wT + 0 * WSZ);
    wtrans_kernel<<<144, 256>>>(theta_w, p_wT + 1 * WSZ);
    wtrans_kernel<<<144, 256>>>(phi_w,   p_wT + 2 * WSZ);
    wtrans_kernel<<<144, 256>>>(gw,      p_wT + 3 * WSZ);
    wtrans_kernel<<<144, 256>>>(conv2_w, p_wT + 4 * WSZ);

    // conv1 + BN1 + ReLU
    conv3x3_kernel<<<BATCH * HW, 256, CONV_SMEM>>>(x, p_wT + 0 * WSZ, nullptr, p_c1);
    bnstats_kernel<<<CH, 256>>>(p_c1, p_mean, p_rstd);
    bnapply_kernel<<<(BATCH * CH * NPIX) / 256, 256>>>(p_c1, p_mean, p_rstd, bn1_g, bn1_b, p_x1);

    // theta / phi / g projections
    conv3x3_kernel<<<BATCH * HW, 256, CONV_SMEM>>>(p_x1, p_wT + 1 * WSZ, theta_b, p_th);
    conv3x3_kernel<<<BATCH * HW, 256, CONV_SMEM>>>(p_x1, p_wT + 2 * WSZ, phi_b,   p_ph);
    conv3x3_kernel<<<BATCH * HW, 256, CONV_SMEM>>>(p_x1, p_wT + 3 * WSZ, gb,      p_gm);

    // attention
    gemm_qk_kernel<<<dim3(64, 64, BATCH), 256>>>(p_th, p_ph, p_f);
    rowstats_kernel<<<BATCH * NPIX, 128>>>(p_f, p_rm, p_rs);
    gemm_pv_kernel<<<dim3(64, BATCH), 256>>>(p_f, p_gm, p_rm, p_rs, p_y);

    // 1x1 W conv + residual
    wconv_kernel<<<(BATCH * NPIX) / 64, 64>>>(p_y, W_w, W_b, x, p_z);

    // conv2 + BN2 + ReLU -> out
    conv3x3_kernel<<<BATCH * HW, 256, CONV_SMEM>>>(p_z, p_wT + 4 * WSZ, nullptr, p_c1);
    bnstats_kernel<<<CH, 256>>>(p_c1, p_mean, p_rstd);
    bnapply_kernel<<<(BATCH * CH * NPIX) / 256, 256>>>(p_c1, p_mean, p_rstd, bn2_g, bn2_b, out);
}

// round 7
// speedup vs baseline: 2.7252x; 2.7252x over previous
#include <cuda_runtime.h>
#include <cuda_bf16.h>
#include <cstdint>

typedef unsigned long long ull;

#define BATCH 4
#define CH    64
#define HW    64
#define NPIX  4096
#define EPSBN 1e-5f

// ---------------------------------------------------------------------------
// Scratch
// ---------------------------------------------------------------------------
__device__ float g_c1raw[BATCH * CH * NPIX];
__device__ float g_x1   [BATCH * CH * NPIX];
__device__ float g_theta[BATCH * CH * NPIX];
__device__ float g_phi  [BATCH * CH * NPIX];
__device__ float g_gm   [BATCH * CH * NPIX];
__device__ float g_y    [BATCH * CH * NPIX];
__device__ float g_z    [BATCH * CH * NPIX];
__device__ float g_f    [(size_t)BATCH * NPIX * NPIX];   // exp(logits), 268 MB
__device__ float g_rowsum[BATCH * NPIX];
__device__ float g_mean[CH];
__device__ float g_rstd[CH];
__device__ float g_wT[5 * 3 * CH * 3 * CH];

// bf16 operands for mma.sync
__device__ __nv_bfloat16 g_thT_hi[BATCH * NPIX * CH];   // [b][n][c]
__device__ __nv_bfloat16 g_thT_lo[BATCH * NPIX * CH];
__device__ __nv_bfloat16 g_phT_hi[BATCH * NPIX * CH];   // [b][m][c]
__device__ __nv_bfloat16 g_phT_lo[BATCH * NPIX * CH];
__device__ __nv_bfloat16 g_g_hi [BATCH * CH * NPIX];    // [b][c][m]
__device__ __nv_bfloat16 g_g_lo [BATCH * CH * NPIX];

// ---------------------------------------------------------------------------
// f32x2 helpers (conv path)
// ---------------------------------------------------------------------------
__device__ __forceinline__ ull pk2(float lo, float hi) {
    ull r; asm("mov.b64 %0, {%1, %2};" : "=l"(r) : "f"(lo), "f"(hi)); return r;
}
__device__ __forceinline__ void fma2(ull& d, ull a, ull b) {
    asm("fma.rn.f32x2 %0, %1, %2, %0;" : "+l"(d) : "l"(a), "l"(b));
}
__device__ __forceinline__ float2 upk2(ull v) {
    float2 r; asm("mov.b64 {%0, %1}, %2;" : "=f"(r.x), "=f"(r.y) : "l"(v)); return r;
}

// ---------------------------------------------------------------------------
// mma.sync helpers (baseline PTX — works on plain sm_103 target)
// ---------------------------------------------------------------------------
__device__ __forceinline__ uint32_t smem_u32(const void* p) {
    uint32_t a;
    asm("{ .reg .u64 t; cvta.to.shared.u64 t, %1; cvt.u32.u64 %0, t; }" : "=r"(a) : "l"(p));
    return a;
}
#define SW128(o) ((o) ^ ((((uint32_t)(o)) >> 3) & 0x70))

__device__ __forceinline__ void ldsm4(uint32_t* r, uint32_t addr) {
    asm volatile("ldmatrix.sync.aligned.m8n8.x4.shared.b16 {%0,%1,%2,%3}, [%4];"
        : "=r"(r[0]), "=r"(r[1]), "=r"(r[2]), "=r"(r[3]) : "r"(addr));
}
__device__ __forceinline__ void mma16816(float* d, const uint32_t* a, const uint32_t* b) {
    asm volatile("mma.sync.aligned.m16n8k16.row.col.f32.bf16.bf16.f32 "
        "{%0,%1,%2,%3},{%4,%5,%6,%7},{%8,%9},{%0,%1,%2,%3};"
        : "+f"(d[0]), "+f"(d[1]), "+f"(d[2]), "+f"(d[3])
        : "r"(a[0]), "r"(a[1]), "r"(a[2]), "r"(a[3]), "r"(b[0]), "r"(b[1]));
}

// ---------------------------------------------------------------------------
// Weight transpose: w[co][ci][kh][kw] -> wT[kh][ci][kw][co]
// ---------------------------------------------------------------------------
__global__ void wtrans_kernel(const float* __restrict__ w, float* __restrict__ wT) {
    int i = blockIdx.x * 256 + threadIdx.x;
    if (i < CH * CH * 9) {
        int kw = i % 3, kh = (i / 3) % 3, ci = (i / 9) % CH, co = i / (9 * CH);
        wT[((kh * CH + ci) * 3 + kw) * CH + co] = w[i];
    }
}

// ---------------------------------------------------------------------------
// Direct 3x3 conv (f32x2), one block = one (b,h) row
// ---------------------------------------------------------------------------
__global__ void __launch_bounds__(256) conv3x3_kernel(
    const float* __restrict__ in, const float* __restrict__ wT,
    const float* __restrict__ bias, float* __restrict__ out)
{
    extern __shared__ float smemf[];
    float* sRow = smemf;
    float* sW   = smemf + 64 * 66;

    const int b   = blockIdx.x >> 6;
    const int h   = blockIdx.x & 63;
    const int tid = threadIdx.x;
    const int cg  = tid >> 4;
    const int pg  = tid & 15;

    ull acc[4][2];
    #pragma unroll
    for (int i = 0; i < 4; ++i) { acc[i][0] = 0ull; acc[i][1] = 0ull; }

    for (int kh = 0; kh < 3; ++kh) {
        const int row = h + kh - 1;
        const float* wsrc = wT + kh * (CH * 3 * CH);
        for (int i = tid; i < CH * 3 * CH; i += 256) sW[i] = wsrc[i];
        if (row >= 0 && row < HW) {
            const float* src = in + (size_t)(b * CH) * NPIX + row * HW;
            for (int i = tid; i < CH * HW; i += 256) {
                int ci = i >> 6, w = i & 63;
                sRow[ci * 66 + 1 + w] = src[(size_t)ci * NPIX + w];
            }
        } else {
            for (int i = tid; i < CH * HW; i += 256) {
                int ci = i >> 6, w = i & 63;
                sRow[ci * 66 + 1 + w] = 0.f;
            }
        }
        if (tid < 64) { sRow[tid * 66] = 0.f; sRow[tid * 66 + 65] = 0.f; }
        __syncthreads();

        #pragma unroll 4
        for (int ci = 0; ci < CH; ++ci) {
            const int rb = ci * 66 + (pg << 1);
            float2 A01 = *(const float2*)&sRow[rb];
            float2 A23 = *(const float2*)&sRow[rb + 2];
            float2 B01 = *(const float2*)&sRow[rb + 32];
            float2 B23 = *(const float2*)&sRow[rb + 34];
            ull pA[3], pB[3];
            pA[0] = pk2(A01.x, A01.y); pA[1] = pk2(A01.y, A23.x); pA[2] = pk2(A23.x, A23.y);
            pB[0] = pk2(B01.x, B01.y); pB[1] = pk2(B01.y, B23.x); pB[2] = pk2(B23.x, B23.y);
            const float* wp = &sW[ci * 192 + (cg << 2)];
            #pragma unroll
            for (int kw = 0; kw < 3; ++kw) {
                float4 wv = *(const float4*)(wp + kw * 64);
                const float wf[4] = {wv.x, wv.y, wv.z, wv.w};
                #pragma unroll
                for (int i = 0; i < 4; ++i) {
                    ull wd = pk2(wf[i], wf[i]);
                    fma2(acc[i][0], wd, pA[kw]);
                    fma2(acc[i][1], wd, pB[kw]);
                }
            }
        }
        __syncthreads();
    }

    const int w0 = pg << 1;
    #pragma unroll
    for (int i = 0; i < 4; ++i) {
        int co = (cg << 2) + i;
        float bv = bias ? bias[co] : 0.f;
        float2 r0 = upk2(acc[i][0]);
        float2 r1 = upk2(acc[i][1]);
        r0.x += bv; r0.y += bv; r1.x += bv; r1.y += bv;
        float* o = out + (size_t)(b * CH + co) * NPIX + h * HW;
        *(float2*)&o[w0]      = r0;
        *(float2*)&o[w0 + 32] = r1;
    }
}

// ---------------------------------------------------------------------------
// BN stats / apply
// ---------------------------------------------------------------------------
__global__ void __launch_bounds__(256) bnstats_kernel(
    const float* __restrict__ v, float* __restrict__ mean, float* __restrict__ rstd)
{
    const int c = blockIdx.x;
    const int tid = threadIdx.x;
    float s = 0.f, s2 = 0.f;
    for (int i = tid; i < BATCH * NPIX; i += 256) {
        int b = i >> 12, p = i & 4095;
        float x = v[(size_t)(b * CH + c) * NPIX + p];
        s += x; s2 += x * x;
    }
    #pragma unroll
    for (int off = 16; off; off >>= 1) {
        s  += __shfl_xor_sync(0xffffffffu, s,  off);
        s2 += __shfl_xor_sync(0xffffffffu, s2, off);
    }
    __shared__ float ws[8], ws2[8];
    if ((tid & 31) == 0) { ws[tid >> 5] = s; ws2[tid >> 5] = s2; }
    __syncthreads();
    if (tid == 0) {
        float S = 0.f, S2 = 0.f;
        #pragma unroll
        for (int i = 0; i < 8; ++i) { S += ws[i]; S2 += ws2[i]; }
        float m = S * (1.f / (BATCH * NPIX));
        float var = S2 * (1.f / (BATCH * NPIX)) - m * m;
        mean[c] = m;
        rstd[c] = rsqrtf(var + EPSBN);
    }
}

__global__ void __launch_bounds__(256) bnapply_kernel(
    const float* __restrict__ v, const float* __restrict__ mean,
    const float* __restrict__ rstd, const float* __restrict__ gamma,
    const float* __restrict__ beta, float* __restrict__ out)
{
    int i = blockIdx.x * 256 + threadIdx.x;
    int c = (i >> 12) & 63;
    float r = (v[i] - mean[c]) * rstd[c] * gamma[c] + beta[c];
    out[i] = fmaxf(r, 0.f);
}

// ---------------------------------------------------------------------------
// Transpose + hi/lo bf16 split: [b][c][n] fp32 -> [b][n][c] bf16 hi/lo
// ---------------------------------------------------------------------------
__global__ void __launch_bounds__(256) convT_kernel(
    const float* __restrict__ in, __nv_bfloat16* __restrict__ hiT,
    __nv_bfloat16* __restrict__ loT)
{
    __shared__ float s[64][65];
    const int b = blockIdx.x >> 6;
    const int n0 = (blockIdx.x & 63) * 64;
    const int tid = threadIdx.x;
    for (int i = tid; i < 4096; i += 256) {
        int c = i >> 6, j = i & 63;
        s[c][j] = in[(((size_t)(b * 64 + c)) << 12) + n0 + j];
    }
    __syncthreads();
    for (int i = tid; i < 4096; i += 256) {
        int nn = i >> 6, c = i & 63;
        float v = s[c][nn];
        __nv_bfloat16 h = __float2bfloat16_rn(v);
        __nv_bfloat16 l = __float2bfloat16_rn(v - __bfloat162float(h));
        size_t o = ((size_t)b * NPIX + n0 + nn) * 64 + c;
        hiT[o] = h; loT[o] = l;
    }
}

__global__ void __launch_bounds__(256) convG_kernel(
    const float* __restrict__ in, __nv_bfloat16* __restrict__ hi,
    __nv_bfloat16* __restrict__ lo)
{
    int i = blockIdx.x * 256 + threadIdx.x;
    float v = in[i];
    __nv_bfloat16 h = __float2bfloat16_rn(v);
    hi[i] = h;
    lo[i] = __float2bfloat16_rn(v - __bfloat162float(h));
}

// ---------------------------------------------------------------------------
// GEMM1 (mma.sync): e[b][n][m] = exp( sum_c theta[c][n] phi[c][m] )
// 128x128 tile, 8 warps (4n x 2m), K=64, 3-pass hi/lo into one fp32 acc.
// Epilogue: exp in regs, direct stores, shfl row-sums + atomicAdd.
// smem: sAh | sAl | sBh | sBl, each 128 rows x 128B (SW128), 64KB total.
// ---------------------------------------------------------------------------
__global__ void __launch_bounds__(256) gemm_qk_mma(
    const __nv_bfloat16* __restrict__ thT_hi, const __nv_bfloat16* __restrict__ thT_lo,
    const __nv_bfloat16* __restrict__ phT_hi, const __nv_bfloat16* __restrict__ phT_lo,
    float* __restrict__ f, float* __restrict__ rowsum)
{
    extern __shared__ __align__(128) char smem[];
    const uint32_t sb = smem_u32(smem);
    const int tid = threadIdx.x, w = tid >> 5, lane = tid & 31;
    const int m0 = blockIdx.x * 128, n0 = blockIdx.y * 128, b = blockIdx.z;
    const int wn = w & 3, wm = w >> 2;

    {
        const uint4* Ah = (const uint4*)(thT_hi + ((size_t)b * NPIX + n0) * 64);
        const uint4* Al = (const uint4*)(thT_lo + ((size_t)b * NPIX + n0) * 64);
        const uint4* Bh = (const uint4*)(phT_hi + ((size_t)b * NPIX + m0) * 64);
        const uint4* Bl = (const uint4*)(phT_lo + ((size_t)b * NPIX + m0) * 64);
        for (int i = tid; i < 1024; i += 256) {
            uint32_t off = SW128((uint32_t)(i >> 3) * 128 + (i & 7) * 16);
            *(uint4*)(smem + off)         = Ah[i];
            *(uint4*)(smem + 16384 + off) = Al[i];
            *(uint4*)(smem + 32768 + off) = Bh[i];
            *(uint4*)(smem + 49152 + off) = Bl[i];
        }
    }
    __syncthreads();

    float acc[2][8][4];
    #pragma unroll
    for (int i = 0; i < 2; ++i)
        #pragma unroll
        for (int j = 0; j < 8; ++j)
            #pragma unroll
            for (int k = 0; k < 4; ++k) acc[i][j][k] = 0.f;

    const int arow = (lane & 15), acol = (lane >> 4);          // A/P frag addr pieces
    const int brow = ((lane >> 4) << 3) + (lane & 7), bcol = ((lane >> 3) & 1);

    #pragma unroll
    for (int k = 0; k < 4; ++k) {
        uint32_t aH[2][4], aL[2][4], bH[4][4], bL[4][4];
        #pragma unroll
        for (int fi = 0; fi < 2; ++fi) {
            uint32_t off = SW128((uint32_t)(wn * 32 + fi * 16 + arow) * 128 + (k * 2 + acol) * 16);
            ldsm4(aH[fi], sb + off);
            ldsm4(aL[fi], sb + 16384 + off);
        }
        #pragma unroll
        for (int q = 0; q < 4; ++q) {
            uint32_t off = SW128((uint32_t)(wm * 64 + q * 16 + brow) * 128 + (k * 2 + bcol) * 16);
            ldsm4(bH[q], sb + 32768 + off);
            ldsm4(bL[q], sb + 49152 + off);
        }
        #pragma unroll
        for (int fi = 0; fi < 2; ++fi)
            #pragma unroll
            for (int q = 0; q < 4; ++q) {
                mma16816(acc[fi][2 * q],     aH[fi], &bH[q][0]);
                mma16816(acc[fi][2 * q + 1], aH[fi], &bH[q][2]);
                mma16816(acc[fi][2 * q],     aH[fi], &bL[q][0]);
                mma16816(acc[fi][2 * q + 1], aH[fi], &bL[q][2]);
                mma16816(acc[fi][2 * q],     aL[fi], &bH[q][0]);
                mma16816(acc[fi][2 * q + 1], aL[fi], &bH[q][2]);
            }
    }

    // epilogue: exp, store, row sums
    float* fbase = f + ((size_t)b << 24);
    #pragma unroll
    for (int fi = 0; fi < 2; ++fi) {
        const int n1 = wn * 32 + fi * 16 + (lane >> 2);
        float s1 = 0.f, s2 = 0.f;
        #pragma unroll
        for (int bj = 0; bj < 8; ++bj) {
            const int ml = wm * 64 + bj * 8 + (lane & 3) * 2;
            float e0 = __expf(acc[fi][bj][0]);
            float e1 = __expf(acc[fi][bj][1]);
            float e2 = __expf(acc[fi][bj][2]);
            float e3 = __expf(acc[fi][bj][3]);
            s1 += e0 + e1; s2 += e2 + e3;
            *(float2*)&fbase[(size_t)(n0 + n1) * NPIX + m0 + ml]     = make_float2(e0, e1);
            *(float2*)&fbase[(size_t)(n0 + n1 + 8) * NPIX + m0 + ml] = make_float2(e2, e3);
        }
        s1 += __shfl_xor_sync(0xffffffffu, s1, 1);
        s1 += __shfl_xor_sync(0xffffffffu, s1, 2);
        s2 += __shfl_xor_sync(0xffffffffu, s2, 1);
        s2 += __shfl_xor_sync(0xffffffffu, s2, 2);
        if ((lane & 3) == 0) {
            atomicAdd(&rowsum[b * NPIX + n0 + n1],     s1);
            atomicAdd(&rowsum[b * NPIX + n0 + n1 + 8], s2);
        }
    }
}

// ---------------------------------------------------------------------------
// GEMM2 (mma.sync): y[b][c][n] = (1/rowsum[n]) * sum_m e[n][m] g[c][m]
// Output tile 128(n) x 64(c), K=4096 in 64-chunks, double-buffered smem,
// register prefetch of the next f/g chunk overlapping the HMMA of the current.
// smem buffers: [buf]{ sP 16KB | sGh 8KB | sGl 8KB } x2 = 64KB; sY reuses buf0.
// ---------------------------------------------------------------------------
__global__ void __launch_bounds__(256) gemm_pv_mma(
    const float* __restrict__ f, const __nv_bfloat16* __restrict__ g_hi,
    const __nv_bfloat16* __restrict__ g_lo, const float* __restrict__ rowsum,
    float* __restrict__ y)
{
    extern __shared__ __align__(128) char smem[];
    const uint32_t sb = smem_u32(smem);
    const int tid = threadIdx.x, w = tid >> 5, lane = tid & 31;
    const int n0 = blockIdx.x * 128, b = blockIdx.y;
    const int wn = w & 3, wc = w >> 2;

    const float* fb = f + ((size_t)b << 24) + (size_t)n0 * NPIX;

    float acc[2][4][4];
    #pragma unroll
    for (int i = 0; i < 2; ++i)
        #pragma unroll
        for (int j = 0; j < 4; ++j)
            #pragma unroll
            for (int k = 0; k < 4; ++k) acc[i][j][k] = 0.f;

    uint4 fr[8];   // raw fp32 f chunk (32 floats)
    uint4 gr[4];   // g hi (2) + lo (2)

    const int arow = (lane & 15), acol = (lane >> 4);
    const int brow = ((lane >> 4) << 3) + (lane & 7), bcol = ((lane >> 3) & 1);

    auto prefetch = [&](int mb) {
        #pragma unroll
        for (int j = 0; j < 4; ++j) {
            int i = tid + 256 * j;
            int row = i >> 3, c8 = i & 7;
            const uint4* p = (const uint4*)&fb[(size_t)row * NPIX + mb + c8 * 8];
            fr[2 * j]     = p[0];
            fr[2 * j + 1] = p[1];
        }
        #pragma unroll
        for (int j = 0; j < 2; ++j) {
            int i = tid + 256 * j;
            int rr = i >> 3, seg = i & 7;
            gr[j]     = *(const uint4*)(g_hi + ((size_t)(b * CH + rr)) * NPIX + mb + seg * 8);
            gr[2 + j] = *(const uint4*)(g_lo + ((size_t)(b * CH + rr)) * NPIX + mb + seg * 8);
        }
    };
    auto store_chunk = [&](int buf) {
        const uint32_t base = buf * 32768;
        #pragma unroll
        for (int j = 0; j < 4; ++j) {
            int i = tid + 256 * j;
            int row = i >> 3, c8 = i & 7;
            float4 x = *(float4*)&fr[2 * j];
            float4 z = *(float4*)&fr[2 * j + 1];
            __nv_bfloat162 h0 = __floats2bfloat162_rn(x.x, x.y);
            __nv_bfloat162 h1 = __floats2bfloat162_rn(x.z, x.w);
            __nv_bfloat162 h2 = __floats2bfloat162_rn(z.x, z.y);
            __nv_bfloat162 h3 = __floats2bfloat162_rn(z.z, z.w);
            uint4 o = make_uint4(*(uint32_t*)&h0, *(uint32_t*)&h1, *(uint32_t*)&h2, *(uint32_t*)&h3);
            *(uint4*)(smem + base + SW128((uint32_t)row * 128 + c8 * 16)) = o;
        }
        #pragma unroll
        for (int j = 0; j < 2; ++j) {
            int i = tid + 256 * j;
            int rr = i >> 3, seg = i & 7;
            uint32_t off = SW128((uint32_t)rr * 128 + seg * 16);
            *(uint4*)(smem + base + 16384 + off) = gr[j];
            *(uint4*)(smem + base + 24576 + off) = gr[2 + j];
        }
    };
    auto do_mma = [&](int buf) {
        const uint32_t base = buf * 32768;
        #pragma unroll
        for (int k = 0; k < 4; ++k) {
            uint32_t aP[2][4], bH[2][4], bL[2][4];
            #pragma unroll
            for (int fi = 0; fi < 2; ++fi) {
                uint32_t off = SW128((uint32_t)(wn * 32 + fi * 16 + arow) * 128 + (k * 2 + acol) * 16);
                ldsm4(aP[fi], sb + base + off);
            }
            #pragma unroll
            for (int q = 0; q < 2; ++q) {
                uint32_t off = SW128((uint32_t)(wc * 32 + q * 16 + brow) * 128 + (k * 2 + bcol) * 16);
                ldsm4(bH[q], sb + base + 16384 + off);
                ldsm4(bL[q], sb + base + 24576 + off);
            }
            #pragma unroll
            for (int fi = 0; fi < 2; ++fi)
                #pragma unroll
                for (int q = 0; q < 2; ++q) {
                    mma16816(acc[fi][2 * q],     aP[fi], &bH[q][0]);
                    mma16816(acc[fi][2 * q + 1], aP[fi], &bH[q][2]);
                    mma16816(acc[fi][2 * q],     aP[fi], &bL[q][0]);
                    mma16816(acc[fi][2 * q + 1], aP[fi], &bL[q][2]);
                }
        }
    };

    prefetch(0);
    store_chunk(0);
    __syncthreads();
    for (int c = 0; c < 64; ++c) {
        const int cur = c & 1;
        if (c < 63) prefetch((c + 1) * 64);
        do_mma(cur);
        if (c < 63) store_chunk(1 - cur);
        __syncthreads();
    }

    // epilogue: scale by 1/rowsum, transpose via smem, coalesced store
    float inv[2][2];
    #pragma unroll
    for (int fi = 0; fi < 2; ++fi) {
        int n1 = wn * 32 + fi * 16 + (lane >> 2);
        inv[fi][0] = 1.f / rowsum[b * NPIX + n0 + n1];
        inv[fi][1] = 1.f / rowsum[b * NPIX + n0 + n1 + 8];
    }
    float* sY = (float*)smem;    // 128 x 65 = 33280 B
    #pragma unroll
    for (int fi = 0; fi < 2; ++fi) {
        int n1 = wn * 32 + fi * 16 + (lane >> 2);
        #pragma unroll
        for (int bj = 0; bj < 4; ++bj) {
            int cl = wc * 32 + bj * 8 + (lane & 3) * 2;
            sY[n1 * 65 + cl]           = acc[fi][bj][0] * inv[fi][0];
            sY[n1 * 65 + cl + 1]       = acc[fi][bj][1] * inv[fi][0];
            sY[(n1 + 8) * 65 + cl]     = acc[fi][bj][2] * inv[fi][1];
            sY[(n1 + 8) * 65 + cl + 1] = acc[fi][bj][3] * inv[fi][1];
        }
    }
    __syncthreads();
    for (int i = tid; i < 8192; i += 256) {
        int c = i >> 7, n = i & 127;
        y[((size_t)(b * CH + c)) * NPIX + n0 + n] = sY[n * 65 + c];
    }
}

// ---------------------------------------------------------------------------
// 1x1 W conv + bias + residual
// ---------------------------------------------------------------------------
__global__ void __launch_bounds__(64) wconv_kernel(
    const float* __restrict__ y, const float* __restrict__ Ww,
    const float* __restrict__ Wb, const float* __restrict__ x,
    float* __restrict__ z)
{
    __shared__ float sW[CH * CH];
    __shared__ float sB[CH];
    const int tid = threadIdx.x;
    for (int i = tid; i < CH * CH; i += 64) sW[i] = Ww[i];
    if (tid < CH) sB[tid] = Wb[tid];
    __syncthreads();

    const int pix = blockIdx.x * 64 + tid;
    const int b = pix >> 12, n = pix & 4095;

    float yv[CH];
    #pragma unroll
    for (int ci = 0; ci < CH; ++ci) yv[ci] = y[(size_t)(b * CH + ci) * NPIX + n];

    #pragma unroll 1
    for (int co = 0; co < CH; ++co) {
        float acc = sB[co];
        #pragma unroll
        for (int ci = 0; ci < CH; ++ci) acc += sW[co * CH + ci] * yv[ci];
        size_t o = (size_t)(b * CH + co) * NPIX + n;
        z[o] = acc + x[o];
    }
}

// ---------------------------------------------------------------------------
// Launch
// ---------------------------------------------------------------------------
extern "C" void kernel_launch(void* const* d_in, const int* in_sizes, int n_in,
                              void* d_out, int out_size)
{
    const float* x       = (const float*)d_in[0];
    const float* conv1_w = (const float*)d_in[1];
    const float* bn1_g   = (const float*)d_in[2];
    const float* bn1_b   = (const float*)d_in[3];
    const float* theta_w = (const float*)d_in[4];
    const float* theta_b = (const float*)d_in[5];
    const float* phi_w   = (const float*)d_in[6];
    const float* phi_b   = (const float*)d_in[7];
    const float* gw      = (const float*)d_in[8];
    const float* gb      = (const float*)d_in[9];
    const float* W_w     = (const float*)d_in[10];
    const float* W_b     = (const float*)d_in[11];
    const float* conv2_w = (const float*)d_in[12];
    const float* bn2_g   = (const float*)d_in[13];
    const float* bn2_b   = (const float*)d_in[14];
    float* out = (float*)d_out;

    float *p_c1, *p_x1, *p_th, *p_ph, *p_gm, *p_y, *p_z, *p_f, *p_rs, *p_mean, *p_rstd, *p_wT;
    __nv_bfloat16 *p_thH, *p_thL, *p_phH, *p_phL, *p_gH, *p_gL;
    cudaGetSymbolAddress((void**)&p_c1,  g_c1raw);
    cudaGetSymbolAddress((void**)&p_x1,  g_x1);
    cudaGetSymbolAddress((void**)&p_th,  g_theta);
    cudaGetSymbolAddress((void**)&p_ph,  g_phi);
    cudaGetSymbolAddress((void**)&p_gm,  g_gm);
    cudaGetSymbolAddress((void**)&p_y,   g_y);
    cudaGetSymbolAddress((void**)&p_z,   g_z);
    cudaGetSymbolAddress((void**)&p_f,   g_f);
    cudaGetSymbolAddress((void**)&p_rs,  g_rowsum);
    cudaGetSymbolAddress((void**)&p_mean, g_mean);
    cudaGetSymbolAddress((void**)&p_rstd, g_rstd);
    cudaGetSymbolAddress((void**)&p_wT,  g_wT);
    cudaGetSymbolAddress((void**)&p_thH, g_thT_hi);
    cudaGetSymbolAddress((void**)&p_thL, g_thT_lo);
    cudaGetSymbolAddress((void**)&p_phH, g_phT_hi);
    cudaGetSymbolAddress((void**)&p_phL, g_phT_lo);
    cudaGetSymbolAddress((void**)&p_gH,  g_g_hi);
    cudaGetSymbolAddress((void**)&p_gL,  g_g_lo);

    const int WSZ = 3 * CH * 3 * CH;
    const int CONV_SMEM = (64 * 66 + CH * 3 * CH) * (int)sizeof(float);
    const int G1_SMEM = 65536;
    const int G2_SMEM = 65536;
    cudaFuncSetAttribute(conv3x3_kernel, cudaFuncAttributeMaxDynamicSharedMemorySize, CONV_SMEM);
    cudaFuncSetAttribute(gemm_qk_mma, cudaFuncAttributeMaxDynamicSharedMemorySize, G1_SMEM);
    cudaFuncSetAttribute(gemm_pv_mma, cudaFuncAttributeMaxDynamicSharedMemorySize, G2_SMEM);

    wtrans_kernel<<<144, 256>>>(conv1_w, p_wT + 0 * WSZ);
    wtrans_kernel<<<144, 256>>>(theta_w, p_wT + 1 * WSZ);
    wtrans_kernel<<<144, 256>>>(phi_w,   p_wT + 2 * WSZ);
    wtrans_kernel<<<144, 256>>>(gw,      p_wT + 3 * WSZ);
    wtrans_kernel<<<144, 256>>>(conv2_w, p_wT + 4 * WSZ);

    // conv1 + BN1 + ReLU
    conv3x3_kernel<<<BATCH * HW, 256, CONV_SMEM>>>(x, p_wT + 0 * WSZ, nullptr, p_c1);
    bnstats_kernel<<<CH, 256>>>(p_c1, p_mean, p_rstd);
    bnapply_kernel<<<(BATCH * CH * NPIX) / 256, 256>>>(p_c1, p_mean, p_rstd, bn1_g, bn1_b, p_x1);

    // projections
    conv3x3_kernel<<<BATCH * HW, 256, CONV_SMEM>>>(p_x1, p_wT + 1 * WSZ, theta_b, p_th);
    conv3x3_kernel<<<BATCH * HW, 256, CONV_SMEM>>>(p_x1, p_wT + 2 * WSZ, phi_b,   p_ph);
    conv3x3_kernel<<<BATCH * HW, 256, CONV_SMEM>>>(p_x1, p_wT + 3 * WSZ, gb,      p_gm);

    // bf16 operand prep
    convT_kernel<<<BATCH * 64, 256>>>(p_th, p_thH, p_thL);
    convT_kernel<<<BATCH * 64, 256>>>(p_ph, p_phH, p_phL);
    convG_kernel<<<(BATCH * CH * NPIX) / 256, 256>>>(p_gm, p_gH, p_gL);

    // attention (mma.sync bf16)
    cudaMemsetAsync(p_rs, 0, BATCH * NPIX * sizeof(float));
    gemm_qk_mma<<<dim3(32, 32, BATCH), 256, G1_SMEM>>>(p_thH, p_thL, p_phH, p_phL, p_f, p_rs);
    gemm_pv_mma<<<dim3(32, BATCH), 256, G2_SMEM>>>(p_f, p_gH, p_gL, p_rs, p_y);

    // 1x1 W conv + residual
    wconv_kernel<<<(BATCH * NPIX) / 64, 64>>>(p_y, W_w, W_b, x, p_z);

    // conv2 + BN2 + ReLU
    conv3x3_kernel<<<BATCH * HW, 256, CONV_SMEM>>>(p_z, p_wT + 4 * WSZ, nullptr, p_c1);
    bnstats_kernel<<<CH, 256>>>(p_c1, p_mean, p_rstd);
    bnapply_kernel<<<(BATCH * CH * NPIX) / 256, 256>>>(p_c1, p_mean, p_rstd, bn2_g, bn2_b, out);
}

// round 8
// speedup vs baseline: 3.4415x; 1.2629x over previous
#include <cuda_runtime.h>
#include <cuda_bf16.h>
#include <cstdint>

typedef unsigned long long ull;

#define BATCH 4
#define CH    64
#define HW    64
#define NPIX  4096
#define EPSBN 1e-5f

// ---------------------------------------------------------------------------
// Scratch
// ---------------------------------------------------------------------------
__device__ float g_c1raw[BATCH * CH * NPIX];
__device__ float g_x1   [BATCH * CH * NPIX];
__device__ float g_theta[BATCH * CH * NPIX];
__device__ float g_phi  [BATCH * CH * NPIX];
__device__ float g_gm   [BATCH * CH * NPIX];
__device__ float g_y    [BATCH * CH * NPIX];
__device__ float g_z    [BATCH * CH * NPIX];
__device__ float g_mean[CH];
__device__ float g_rstd[CH];
__device__ float g_wT[5 * 3 * CH * 3 * CH];

// bf16 operands for mma.sync
__device__ __nv_bfloat16 g_thT_hi[BATCH * NPIX * CH];   // [b][n][c]
__device__ __nv_bfloat16 g_thT_lo[BATCH * NPIX * CH];
__device__ __nv_bfloat16 g_phT_hi[BATCH * NPIX * CH];   // [b][m][c]
__device__ __nv_bfloat16 g_phT_lo[BATCH * NPIX * CH];
__device__ __nv_bfloat16 g_g_hi [BATCH * CH * NPIX];    // [b][c][m]
__device__ __nv_bfloat16 g_g_lo [BATCH * CH * NPIX];

// ---------------------------------------------------------------------------
// f32x2 helpers (conv path)
// ---------------------------------------------------------------------------
__device__ __forceinline__ ull pk2(float lo, float hi) {
    ull r; asm("mov.b64 %0, {%1, %2};" : "=l"(r) : "f"(lo), "f"(hi)); return r;
}
__device__ __forceinline__ void fma2(ull& d, ull a, ull b) {
    asm("fma.rn.f32x2 %0, %1, %2, %0;" : "+l"(d) : "l"(a), "l"(b));
}
__device__ __forceinline__ float2 upk2(ull v) {
    float2 r; asm("mov.b64 {%0, %1}, %2;" : "=f"(r.x), "=f"(r.y) : "l"(v)); return r;
}

// ---------------------------------------------------------------------------
// mma.sync / cp.async helpers (baseline PTX, plain sm_103 target)
// ---------------------------------------------------------------------------
__device__ __forceinline__ uint32_t smem_u32(const void* p) {
    uint32_t a;
    asm("{ .reg .u64 t; cvta.to.shared.u64 t, %1; cvt.u32.u64 %0, t; }" : "=r"(a) : "l"(p));
    return a;
}
#define SW128(o) ((o) ^ ((((uint32_t)(o)) >> 3) & 0x70))

__device__ __forceinline__ void ldsm4(uint32_t* r, uint32_t addr) {
    asm volatile("ldmatrix.sync.aligned.m8n8.x4.shared.b16 {%0,%1,%2,%3}, [%4];"
        : "=r"(r[0]), "=r"(r[1]), "=r"(r[2]), "=r"(r[3]) : "r"(addr));
}
__device__ __forceinline__ void mma16816(float* d, const uint32_t* a, const uint32_t* b) {
    asm volatile("mma.sync.aligned.m16n8k16.row.col.f32.bf16.bf16.f32 "
        "{%0,%1,%2,%3},{%4,%5,%6,%7},{%8,%9},{%0,%1,%2,%3};"
        : "+f"(d[0]), "+f"(d[1]), "+f"(d[2]), "+f"(d[3])
        : "r"(a[0]), "r"(a[1]), "r"(a[2]), "r"(a[3]), "r"(b[0]), "r"(b[1]));
}
__device__ __forceinline__ void cpasync16(uint32_t dst, const void* src) {
    asm volatile("cp.async.cg.shared.global [%0], [%1], 16;" :: "r"(dst), "l"(src));
}
__device__ __forceinline__ void cpasync_commit() {
    asm volatile("cp.async.commit_group;" ::: "memory");
}
__device__ __forceinline__ void cpasync_wait0() {
    asm volatile("cp.async.wait_group 0;" ::: "memory");
}

// ---------------------------------------------------------------------------
// Weight transpose (all 5 sets in one launch): w[co][ci][kh][kw] -> wT[kh][ci][kw][co]
// ---------------------------------------------------------------------------
__global__ void wtrans_all_kernel(
    const float* __restrict__ w0, const float* __restrict__ w1,
    const float* __restrict__ w2, const float* __restrict__ w3,
    const float* __restrict__ w4, float* __restrict__ wT)
{
    const float* ws[5] = {w0, w1, w2, w3, w4};
    const float* w = ws[blockIdx.y];
    float* o = wT + blockIdx.y * (3 * CH * 3 * CH);
    int i = blockIdx.x * 256 + threadIdx.x;
    if (i < CH * CH * 9) {
        int kw = i % 3, kh = (i / 3) % 3, ci = (i / 9) % CH, co = i / (9 * CH);
        o[((kh * CH + ci) * 3 + kw) * CH + co] = w[i];
    }
}

// ---------------------------------------------------------------------------
// Direct 3x3 conv (f32x2), one block = one (b,h) row
// ---------------------------------------------------------------------------
__global__ void __launch_bounds__(256) conv3x3_kernel(
    const float* __restrict__ in, const float* __restrict__ wT,
    const float* __restrict__ bias, float* __restrict__ out)
{
    extern __shared__ float smemf[];
    float* sRow = smemf;
    float* sW   = smemf + 64 * 66;

    const int b   = blockIdx.x >> 6;
    const int h   = blockIdx.x & 63;
    const int tid = threadIdx.x;
    const int cg  = tid >> 4;
    const int pg  = tid & 15;

    ull acc[4][2];
    #pragma unroll
    for (int i = 0; i < 4; ++i) { acc[i][0] = 0ull; acc[i][1] = 0ull; }

    for (int kh = 0; kh < 3; ++kh) {
        const int row = h + kh - 1;
        const float* wsrc = wT + kh * (CH * 3 * CH);
        for (int i = tid; i < CH * 3 * CH; i += 256) sW[i] = wsrc[i];
        if (row >= 0 && row < HW) {
            const float* src = in + (size_t)(b * CH) * NPIX + row * HW;
            for (int i = tid; i < CH * HW; i += 256) {
                int ci = i >> 6, w = i & 63;
                sRow[ci * 66 + 1 + w] = src[(size_t)ci * NPIX + w];
            }
        } else {
            for (int i = tid; i < CH * HW; i += 256) {
                int ci = i >> 6, w = i & 63;
                sRow[ci * 66 + 1 + w] = 0.f;
            }
        }
        if (tid < 64) { sRow[tid * 66] = 0.f; sRow[tid * 66 + 65] = 0.f; }
        __syncthreads();

        #pragma unroll 4
        for (int ci = 0; ci < CH; ++ci) {
            const int rb = ci * 66 + (pg << 1);
            float2 A01 = *(const float2*)&sRow[rb];
            float2 A23 = *(const float2*)&sRow[rb + 2];
            float2 B01 = *(const float2*)&sRow[rb + 32];
            float2 B23 = *(const float2*)&sRow[rb + 34];
            ull pA[3], pB[3];
            pA[0] = pk2(A01.x, A01.y); pA[1] = pk2(A01.y, A23.x); pA[2] = pk2(A23.x, A23.y);
            pB[0] = pk2(B01.x, B01.y); pB[1] = pk2(B01.y, B23.x); pB[2] = pk2(B23.x, B23.y);
            const float* wp = &sW[ci * 192 + (cg << 2)];
            #pragma unroll
            for (int kw = 0; kw < 3; ++kw) {
                float4 wv = *(const float4*)(wp + kw * 64);
                const float wf[4] = {wv.x, wv.y, wv.z, wv.w};
                #pragma unroll
                for (int i = 0; i < 4; ++i) {
                    ull wd = pk2(wf[i], wf[i]);
                    fma2(acc[i][0], wd, pA[kw]);
                    fma2(acc[i][1], wd, pB[kw]);
                }
            }
        }
        __syncthreads();
    }

    const int w0 = pg << 1;
    #pragma unroll
    for (int i = 0; i < 4; ++i) {
        int co = (cg << 2) + i;
        float bv = bias ? bias[co] : 0.f;
        float2 r0 = upk2(acc[i][0]);
        float2 r1 = upk2(acc[i][1]);
        r0.x += bv; r0.y += bv; r1.x += bv; r1.y += bv;
        float* o = out + (size_t)(b * CH + co) * NPIX + h * HW;
        *(float2*)&o[w0]      = r0;
        *(float2*)&o[w0 + 32] = r1;
    }
}

// ---------------------------------------------------------------------------
// BN stats / apply
// ---------------------------------------------------------------------------
__global__ void __launch_bounds__(256) bnstats_kernel(
    const float* __restrict__ v, float* __restrict__ mean, float* __restrict__ rstd)
{
    const int c = blockIdx.x;
    const int tid = threadIdx.x;
    float s = 0.f, s2 = 0.f;
    for (int i = tid; i < BATCH * NPIX; i += 256) {
        int b = i >> 12, p = i & 4095;
        float x = v[(size_t)(b * CH + c) * NPIX + p];
        s += x; s2 += x * x;
    }
    #pragma unroll
    for (int off = 16; off; off >>= 1) {
        s  += __shfl_xor_sync(0xffffffffu, s,  off);
        s2 += __shfl_xor_sync(0xffffffffu, s2, off);
    }
    __shared__ float ws[8], ws2[8];
    if ((tid & 31) == 0) { ws[tid >> 5] = s; ws2[tid >> 5] = s2; }
    __syncthreads();
    if (tid == 0) {
        float S = 0.f, S2 = 0.f;
        #pragma unroll
        for (int i = 0; i < 8; ++i) { S += ws[i]; S2 += ws2[i]; }
        float m = S * (1.f / (BATCH * NPIX));
        float var = S2 * (1.f / (BATCH * NPIX)) - m * m;
        mean[c] = m;
        rstd[c] = rsqrtf(var + EPSBN);
    }
}

__global__ void __launch_bounds__(256) bnapply_kernel(
    const float* __restrict__ v, const float* __restrict__ mean,
    const float* __restrict__ rstd, const float* __restrict__ gamma,
    const float* __restrict__ beta, float* __restrict__ out)
{
    int i = blockIdx.x * 256 + threadIdx.x;
    int c = (i >> 12) & 63;
    float r = (v[i] - mean[c]) * rstd[c] * gamma[c] + beta[c];
    out[i] = fmaxf(r, 0.f);
}

// ---------------------------------------------------------------------------
// Transpose + hi/lo bf16 split: [b][c][n] fp32 -> [b][n][c] bf16 hi/lo
// ---------------------------------------------------------------------------
__global__ void __launch_bounds__(256) convT_kernel(
    const float* __restrict__ in, __nv_bfloat16* __restrict__ hiT,
    __nv_bfloat16* __restrict__ loT)
{
    __shared__ float s[64][65];
    const int b = blockIdx.x >> 6;
    const int n0 = (blockIdx.x & 63) * 64;
    const int tid = threadIdx.x;
    for (int i = tid; i < 4096; i += 256) {
        int c = i >> 6, j = i & 63;
        s[c][j] = in[(((size_t)(b * 64 + c)) << 12) + n0 + j];
    }
    __syncthreads();
    for (int i = tid; i < 4096; i += 256) {
        int nn = i >> 6, c = i & 63;
        float v = s[c][nn];
        __nv_bfloat16 h = __float2bfloat16_rn(v);
        __nv_bfloat16 l = __float2bfloat16_rn(v - __bfloat162float(h));
        size_t o = ((size_t)b * NPIX + n0 + nn) * 64 + c;
        hiT[o] = h; loT[o] = l;
    }
}

__global__ void __launch_bounds__(256) convG_kernel(
    const float* __restrict__ in, __nv_bfloat16* __restrict__ hi,
    __nv_bfloat16* __restrict__ lo)
{
    int i = blockIdx.x * 256 + threadIdx.x;
    float v = in[i];
    __nv_bfloat16 h = __float2bfloat16_rn(v);
    hi[i] = h;
    lo[i] = __float2bfloat16_rn(v - __bfloat162float(h));
}

// ---------------------------------------------------------------------------
// Fused attention: y[b][c][n] = softmax_m(theta.T phi)[n,m] @ g[c,m] / rowsum
// One block = 128 n-rows x full softmax row (m=4096) x 64 c outputs.
// S = theta.T phi chunkwise via HMMA (3-pass hi/lo), exp in regs, P staged in
// smem bf16, immediately consumed by P@g HMMA (2-pass g hi/lo), fp32 acc.
// Row sums accumulate in registers; divide at the end. No f tensor in gmem.
// smem: sTh(hi,lo) 32KB | buf0 64KB | buf1 64KB | P 32KB | RS 512B = 197KB.
// ---------------------------------------------------------------------------
#define FA_TH_HI 0
#define FA_TH_LO 16384
#define FA_BUF0  32768
#define FA_BUF1  98304
#define FA_PH    0          // in-buf: phi hi
#define FA_PL    16384      // in-buf: phi lo
#define FA_GH    32768      // in-buf: g hi (2 panels x 8KB)
#define FA_GL    49152      // in-buf: g lo
#define FA_P     163840     // P staging (2 panels x 16KB)
#define FA_RS    196608
#define FA_SMEM  197120

__global__ void __launch_bounds__(256, 1) attn_fused_kernel(
    const __nv_bfloat16* __restrict__ thT_hi, const __nv_bfloat16* __restrict__ thT_lo,
    const __nv_bfloat16* __restrict__ phT_hi, const __nv_bfloat16* __restrict__ phT_lo,
    const __nv_bfloat16* __restrict__ g_hi,   const __nv_bfloat16* __restrict__ g_lo,
    float* __restrict__ y)
{
    extern __shared__ __align__(128) char smem[];
    const uint32_t sb = smem_u32(smem);
    const int tid = threadIdx.x, w = tid >> 5, lane = tid & 31;
    const int n0 = blockIdx.x * 128, b = blockIdx.y;
    const int wn = w & 3, wm = w >> 2;          // wm doubles as wc for PV

    float* sRS = (float*)(smem + FA_RS);
    if (tid < 128) sRS[tid] = 0.f;

    // theta tile (fixed for this block): 128 n-rows x 64c, hi+lo
    {
        const uint4* Ah = (const uint4*)(thT_hi + ((size_t)b * NPIX + n0) * 64);
        const uint4* Al = (const uint4*)(thT_lo + ((size_t)b * NPIX + n0) * 64);
        for (int i = tid; i < 1024; i += 256) {
            uint32_t off = SW128((uint32_t)(i >> 3) * 128 + (i & 7) * 16);
            *(uint4*)(smem + FA_TH_HI + off) = Ah[i];
            *(uint4*)(smem + FA_TH_LO + off) = Al[i];
        }
    }

    const char* phh = (const char*)(phT_hi + (size_t)b * NPIX * 64);
    const char* phl = (const char*)(phT_lo + (size_t)b * NPIX * 64);

    // async-load one 128-wide m-chunk (phi 128x64 hi/lo + g 64x128 hi/lo)
    auto load_chunk = [&](int mb, uint32_t buf) {
        const char* ph = phh + (size_t)mb * 128;
        const char* pl = phl + (size_t)mb * 128;
        for (int i = tid; i < 1024; i += 256) {
            uint32_t off = SW128((uint32_t)(i >> 3) * 128 + (i & 7) * 16);
            cpasync16(sb + buf + FA_PH + off, ph + i * 16);
            cpasync16(sb + buf + FA_PL + off, pl + i * 16);
        }
        for (int i = tid; i < 1024; i += 256) {
            int row = i >> 4, seg = i & 15;
            uint32_t off = (uint32_t)(seg >> 3) * 8192 + SW128((uint32_t)row * 128 + (seg & 7) * 16);
            const size_t go = ((size_t)(b * CH + row)) * NPIX + mb + seg * 8;
            cpasync16(sb + buf + FA_GH + off, g_hi + go);
            cpasync16(sb + buf + FA_GL + off, g_lo + go);
        }
        cpasync_commit();
    };

    load_chunk(0, FA_BUF0);
    cpasync_wait0();
    __syncthreads();

    float acco[2][4][4];
    #pragma unroll
    for (int i = 0; i < 2; ++i)
        #pragma unroll
        for (int j = 0; j < 4; ++j)
            #pragma unroll
            for (int k = 0; k < 4; ++k) acco[i][j][k] = 0.f;
    float rs[2][2] = {{0.f, 0.f}, {0.f, 0.f}};

    const int arow = (lane & 15), acol = (lane >> 4);
    const int brow = ((lane >> 4) << 3) + (lane & 7), bcol = ((lane >> 3) & 1);

    for (int c = 0; c < 32; ++c) {
        const uint32_t buf  = (c & 1) ? FA_BUF1 : FA_BUF0;
        const uint32_t nbuf = (c & 1) ? FA_BUF0 : FA_BUF1;
        if (c < 31) load_chunk((c + 1) * 128, nbuf);

        // ---- S chunk: 128n x 128m, K=64, 3-pass hi/lo ----
        float accs[2][8][4];
        #pragma unroll
        for (int i = 0; i < 2; ++i)
            #pragma unroll
            for (int j = 0; j < 8; ++j)
                #pragma unroll
                for (int k = 0; k < 4; ++k) accs[i][j][k] = 0.f;

        #pragma unroll
        for (int k = 0; k < 4; ++k) {
            uint32_t aH[2][4], aL[2][4], bH[4][4], bL[4][4];
            #pragma unroll
            for (int fi = 0; fi < 2; ++fi) {
                uint32_t off = SW128((uint32_t)(wn * 32 + fi * 16 + arow) * 128 + (k * 2 + acol) * 16);
                ldsm4(aH[fi], sb + FA_TH_HI + off);
                ldsm4(aL[fi], sb + FA_TH_LO + off);
            }
            #pragma unroll
            for (int q = 0; q < 4; ++q) {
                uint32_t off = SW128((uint32_t)(wm * 64 + q * 16 + brow) * 128 + (k * 2 + bcol) * 16);
                ldsm4(bH[q], sb + buf + FA_PH + off);
                ldsm4(bL[q], sb + buf + FA_PL + off);
            }
            #pragma unroll
            for (int fi = 0; fi < 2; ++fi)
                #pragma unroll
                for (int q = 0; q < 4; ++q) {
                    mma16816(accs[fi][2 * q],     aH[fi], &bH[q][0]);
                    mma16816(accs[fi][2 * q + 1], aH[fi], &bH[q][2]);
                    mma16816(accs[fi][2 * q],     aH[fi], &bL[q][0]);
                    mma16816(accs[fi][2 * q + 1], aH[fi], &bL[q][2]);
                    mma16816(accs[fi][2 * q],     aL[fi], &bH[q][0]);
                    mma16816(accs[fi][2 * q + 1], aL[fi], &bH[q][2]);
                }
        }

        // ---- exp -> P (bf16, smem panels) + rowsum ----
        #pragma unroll
        for (int fi = 0; fi < 2; ++fi) {
            const int n1 = wn * 32 + fi * 16 + (lane >> 2);
            #pragma unroll
            for (int bj = 0; bj < 8; ++bj) {
                const int ml = wm * 64 + bj * 8 + (lane & 3) * 2;
                const uint32_t pan = (uint32_t)(ml >> 6) * 16384;
                const int col = ml & 63;
                float e0 = __expf(accs[fi][bj][0]);
                float e1 = __expf(accs[fi][bj][1]);
                float e2 = __expf(accs[fi][bj][2]);
                float e3 = __expf(accs[fi][bj][3]);
                rs[fi][0] += e0 + e1; rs[fi][1] += e2 + e3;
                __nv_bfloat162 p01 = __floats2bfloat162_rn(e0, e1);
                __nv_bfloat162 p23 = __floats2bfloat162_rn(e2, e3);
                *(uint32_t*)(smem + FA_P + pan + SW128((uint32_t)n1 * 128 + col * 2))       = *(uint32_t*)&p01;
                *(uint32_t*)(smem + FA_P + pan + SW128((uint32_t)(n1 + 8) * 128 + col * 2)) = *(uint32_t*)&p23;
            }
        }
        __syncthreads();   // P fully written before any warp's PV reads

        // ---- PV: P(128n x 128m) @ g(64c x 128m)^T, 2-pass g hi/lo ----
        #pragma unroll
        for (int kk = 0; kk < 8; ++kk) {
            const uint32_t panA = (uint32_t)(kk >> 2) * 16384;
            const uint32_t panB = (uint32_t)(kk >> 2) * 8192;
            const int kc = kk & 3;
            uint32_t aP[2][4], bH[2][4], bL[2][4];
            #pragma unroll
            for (int fi = 0; fi < 2; ++fi) {
                uint32_t off = SW128((uint32_t)(wn * 32 + fi * 16 + arow) * 128 + (kc * 2 + acol) * 16);
                ldsm4(aP[fi], sb + FA_P + panA + off);
            }
            #pragma unroll
            for (int q = 0; q < 2; ++q) {
                uint32_t off = SW128((uint32_t)(wm * 32 + q * 16 + brow) * 128 + (kc * 2 + bcol) * 16);
                ldsm4(bH[q], sb + buf + FA_GH + panB + off);
                ldsm4(bL[q], sb + buf + FA_GL + panB + off);
            }
            #pragma unroll
            for (int fi = 0; fi < 2; ++fi)
                #pragma unroll
                for (int q = 0; q < 2; ++q) {
                    mma16816(acco[fi][2 * q],     aP[fi], &bH[q][0]);
                    mma16816(acco[fi][2 * q + 1], aP[fi], &bH[q][2]);
                    mma16816(acco[fi][2 * q],     aP[fi], &bL[q][0]);
                    mma16816(acco[fi][2 * q + 1], aP[fi], &bL[q][2]);
                }
        }

        cpasync_wait0();
        __syncthreads();   // next chunk landed; P free to overwrite
    }

    // ---- rowsum reduce (lanes, then cross-warp via smem atomics) ----
    #pragma unroll
    for (int fi = 0; fi < 2; ++fi) {
        const int n1 = wn * 32 + fi * 16 + (lane >> 2);
        float s1 = rs[fi][0], s2 = rs[fi][1];
        s1 += __shfl_xor_sync(0xffffffffu, s1, 1);
        s1 += __shfl_xor_sync(0xffffffffu, s1, 2);
        s2 += __shfl_xor_sync(0xffffffffu, s2, 1);
        s2 += __shfl_xor_sync(0xffffffffu, s2, 2);
        if ((lane & 3) == 0) {
            atomicAdd(&sRS[n1], s1);
            atomicAdd(&sRS[n1 + 8], s2);
        }
    }
    __syncthreads();

    // ---- scale + transpose + store y ----
    float inv[2][2];
    #pragma unroll
    for (int fi = 0; fi < 2; ++fi) {
        int n1 = wn * 32 + fi * 16 + (lane >> 2);
        inv[fi][0] = 1.f / sRS[n1];
        inv[fi][1] = 1.f / sRS[n1 + 8];
    }
    float* sY = (float*)smem;    // reuse sTh region (128 x 65 floats)
    #pragma unroll
    for (int fi = 0; fi < 2; ++fi) {
        int n1 = wn * 32 + fi * 16 + (lane >> 2);
        #pragma unroll
        for (int bj = 0; bj < 4; ++bj) {
            int cl = wm * 32 + bj * 8 + (lane & 3) * 2;
            sY[n1 * 65 + cl]           = acco[fi][bj][0] * inv[fi][0];
            sY[n1 * 65 + cl + 1]       = acco[fi][bj][1] * inv[fi][0];
            sY[(n1 + 8) * 65 + cl]     = acco[fi][bj][2] * inv[fi][1];
            sY[(n1 + 8) * 65 + cl + 1] = acco[fi][bj][3] * inv[fi][1];
        }
    }
    __syncthreads();
    for (int i = tid; i < 8192; i += 256) {
        int c = i >> 7, n = i & 127;
        y[((size_t)(b * CH + c)) * NPIX + n0 + n] = sY[n * 65 + c];
    }
}

// ---------------------------------------------------------------------------
// 1x1 W conv + bias + residual
// ---------------------------------------------------------------------------
__global__ void __launch_bounds__(64) wconv_kernel(
    const float* __restrict__ y, const float* __restrict__ Ww,
    const float* __restrict__ Wb, const float* __restrict__ x,
    float* __restrict__ z)
{
    __shared__ float sW[CH * CH];
    __shared__ float sB[CH];
    const int tid = threadIdx.x;
    for (int i = tid; i < CH * CH; i += 64) sW[i] = Ww[i];
    if (tid < CH) sB[tid] = Wb[tid];
    __syncthreads();

    const int pix = blockIdx.x * 64 + tid;
    const int b = pix >> 12, n = pix & 4095;

    float yv[CH];
    #pragma unroll
    for (int ci = 0; ci < CH; ++ci) yv[ci] = y[(size_t)(b * CH + ci) * NPIX + n];

    #pragma unroll 1
    for (int co = 0; co < CH; ++co) {
        float acc = sB[co];
        #pragma unroll
        for (int ci = 0; ci < CH; ++ci) acc += sW[co * CH + ci] * yv[ci];
        size_t o = (size_t)(b * CH + co) * NPIX + n;
        z[o] = acc + x[o];
    }
}

// ---------------------------------------------------------------------------
// Launch
// ---------------------------------------------------------------------------
extern "C" void kernel_launch(void* const* d_in, const int* in_sizes, int n_in,
                              void* d_out, int out_size)
{
    const float* x       = (const float*)d_in[0];
    const float* conv1_w = (const float*)d_in[1];
    const float* bn1_g   = (const float*)d_in[2];
    const float* bn1_b   = (const float*)d_in[3];
    const float* theta_w = (const float*)d_in[4];
    const float* theta_b = (const float*)d_in[5];
    const float* phi_w   = (const float*)d_in[6];
    const float* phi_b   = (const float*)d_in[7];
    const float* gw      = (const float*)d_in[8];
    const float* gb      = (const float*)d_in[9];
    const float* W_w     = (const float*)d_in[10];
    const float* W_b     = (const float*)d_in[11];
    const float* conv2_w = (const float*)d_in[12];
    const float* bn2_g   = (const float*)d_in[13];
    const float* bn2_b   = (const float*)d_in[14];
    float* out = (float*)d_out;

    float *p_c1, *p_x1, *p_th, *p_ph, *p_gm, *p_y, *p_z, *p_mean, *p_rstd, *p_wT;
    __nv_bfloat16 *p_thH, *p_thL, *p_phH, *p_phL, *p_gH, *p_gL;
    cudaGetSymbolAddress((void**)&p_c1,  g_c1raw);
    cudaGetSymbolAddress((void**)&p_x1,  g_x1);
    cudaGetSymbolAddress((void**)&p_th,  g_theta);
    cudaGetSymbolAddress((void**)&p_ph,  g_phi);
    cudaGetSymbolAddress((void**)&p_gm,  g_gm);
    cudaGetSymbolAddress((void**)&p_y,   g_y);
    cudaGetSymbolAddress((void**)&p_z,   g_z);
    cudaGetSymbolAddress((void**)&p_mean, g_mean);
    cudaGetSymbolAddress((void**)&p_rstd, g_rstd);
    cudaGetSymbolAddress((void**)&p_wT,  g_wT);
    cudaGetSymbolAddress((void**)&p_thH, g_thT_hi);
    cudaGetSymbolAddress((void**)&p_thL, g_thT_lo);
    cudaGetSymbolAddress((void**)&p_phH, g_phT_hi);
    cudaGetSymbolAddress((void**)&p_phL, g_phT_lo);
    cudaGetSymbolAddress((void**)&p_gH,  g_g_hi);
    cudaGetSymbolAddress((void**)&p_gL,  g_g_lo);

    const int WSZ = 3 * CH * 3 * CH;
    const int CONV_SMEM = (64 * 66 + CH * 3 * CH) * (int)sizeof(float);
    cudaFuncSetAttribute(conv3x3_kernel, cudaFuncAttributeMaxDynamicSharedMemorySize, CONV_SMEM);
    cudaFuncSetAttribute(attn_fused_kernel, cudaFuncAttributeMaxDynamicSharedMemorySize, FA_SMEM);

    wtrans_all_kernel<<<dim3(144, 5), 256>>>(conv1_w, theta_w, phi_w, gw, conv2_w, p_wT);

    // conv1 + BN1 + ReLU
    conv3x3_kernel<<<BATCH * HW, 256, CONV_SMEM>>>(x, p_wT + 0 * WSZ, nullptr, p_c1);
    bnstats_kernel<<<CH, 256>>>(p_c1, p_mean, p_rstd);
    bnapply_kernel<<<(BATCH * CH * NPIX) / 256, 256>>>(p_c1, p_mean, p_rstd, bn1_g, bn1_b, p_x1);

    // projections
    conv3x3_kernel<<<BATCH * HW, 256, CONV_SMEM>>>(p_x1, p_wT + 1 * WSZ, theta_b, p_th);
    conv3x3_kernel<<<BATCH * HW, 256, CONV_SMEM>>>(p_x1, p_wT + 2 * WSZ, phi_b,   p_ph);
    conv3x3_kernel<<<BATCH * HW, 256, CONV_SMEM>>>(p_x1, p_wT + 3 * WSZ, gb,      p_gm);

    // bf16 operand prep
    convT_kernel<<<BATCH * 64, 256>>>(p_th, p_thH, p_thL);
    convT_kernel<<<BATCH * 64, 256>>>(p_ph, p_phH, p_phL);
    convG_kernel<<<(BATCH * CH * NPIX) / 256, 256>>>(p_gm, p_gH, p_gL);

    // fused attention (no f tensor)
    attn_fused_kernel<<<dim3(32, BATCH), 256, FA_SMEM>>>(
        p_thH, p_thL, p_phH, p_phL, p_gH, p_gL, p_y);

    // 1x1 W conv + residual
    wconv_kernel<<<(BATCH * NPIX) / 64, 64>>>(p_y, W_w, W_b, x, p_z);

    // conv2 + BN2 + ReLU
    conv3x3_kernel<<<BATCH * HW, 256, CONV_SMEM>>>(p_z, p_wT + 4 * WSZ, nullptr, p_c1);
    bnstats_kernel<<<CH, 256>>>(p_c1, p_mean, p_rstd);
    bnapply_kernel<<<(BATCH * CH * NPIX) / 256, 256>>>(p_c1, p_mean, p_rstd, bn2_g, bn2_b, out);
}

// round 9
// speedup vs baseline: 3.7479x; 1.0890x over previous
#include <cuda_runtime.h>
#include <cuda_bf16.h>
#include <cstdint>

typedef unsigned long long ull;

#define BATCH 4
#define CH    64
#define HW    64
#define NPIX  4096
#define EPSBN 1e-5f

// ---------------------------------------------------------------------------
// Scratch
// ---------------------------------------------------------------------------
__device__ float g_c1raw[BATCH * CH * NPIX];
__device__ float g_z    [BATCH * CH * NPIX];
__device__ float g_mean[CH];
__device__ float g_rstd[CH];
__device__ float g_stats[2 * CH];              // s1 | s2
__device__ float g_wT[5 * 3 * CH * 3 * CH];

// bf16 operands for mma.sync
__device__ __nv_bfloat16 g_thT_hi[BATCH * NPIX * CH];   // [b][n][c]
__device__ __nv_bfloat16 g_thT_lo[BATCH * NPIX * CH];
__device__ __nv_bfloat16 g_phT_hi[BATCH * NPIX * CH];   // [b][m][c]
__device__ __nv_bfloat16 g_phT_lo[BATCH * NPIX * CH];
__device__ __nv_bfloat16 g_g_hi [BATCH * CH * NPIX];    // [b][c][m]
__device__ __nv_bfloat16 g_g_lo [BATCH * CH * NPIX];

// ---------------------------------------------------------------------------
// f32x2 helpers
// ---------------------------------------------------------------------------
__device__ __forceinline__ ull pk2(float lo, float hi) {
    ull r; asm("mov.b64 %0, {%1, %2};" : "=l"(r) : "f"(lo), "f"(hi)); return r;
}
__device__ __forceinline__ void fma2(ull& d, ull a, ull b) {
    asm("fma.rn.f32x2 %0, %1, %2, %0;" : "+l"(d) : "l"(a), "l"(b));
}
__device__ __forceinline__ float2 upk2(ull v) {
    float2 r; asm("mov.b64 {%0, %1}, %2;" : "=f"(r.x), "=f"(r.y) : "l"(v)); return r;
}

// ---------------------------------------------------------------------------
// mma.sync / cp.async helpers (baseline PTX, plain sm_103 target)
// ---------------------------------------------------------------------------
__device__ __forceinline__ uint32_t smem_u32(const void* p) {
    uint32_t a;
    asm("{ .reg .u64 t; cvta.to.shared.u64 t, %1; cvt.u32.u64 %0, t; }" : "=r"(a) : "l"(p));
    return a;
}
#define SW128(o) ((o) ^ ((((uint32_t)(o)) >> 3) & 0x70))

__device__ __forceinline__ void ldsm4(uint32_t* r, uint32_t addr) {
    asm volatile("ldmatrix.sync.aligned.m8n8.x4.shared.b16 {%0,%1,%2,%3}, [%4];"
        : "=r"(r[0]), "=r"(r[1]), "=r"(r[2]), "=r"(r[3]) : "r"(addr));
}
__device__ __forceinline__ void mma16816(float* d, const uint32_t* a, const uint32_t* b) {
    asm volatile("mma.sync.aligned.m16n8k16.row.col.f32.bf16.bf16.f32 "
        "{%0,%1,%2,%3},{%4,%5,%6,%7},{%8,%9},{%0,%1,%2,%3};"
        : "+f"(d[0]), "+f"(d[1]), "+f"(d[2]), "+f"(d[3])
        : "r"(a[0]), "r"(a[1]), "r"(a[2]), "r"(a[3]), "r"(b[0]), "r"(b[1]));
}
__device__ __forceinline__ void cpasync16(uint32_t dst, const void* src) {
    asm volatile("cp.async.cg.shared.global [%0], [%1], 16;" :: "r"(dst), "l"(src));
}
__device__ __forceinline__ void cpasync_commit() {
    asm volatile("cp.async.commit_group;" ::: "memory");
}
__device__ __forceinline__ void cpasync_wait0() {
    asm volatile("cp.async.wait_group 0;" ::: "memory");
}

// ---------------------------------------------------------------------------
// Weight transpose (all 5 sets): w[co][ci][kh][kw] -> wT[kh][ci][kw][co]
// ---------------------------------------------------------------------------
__global__ void wtrans_all_kernel(
    const float* __restrict__ w0, const float* __restrict__ w1,
    const float* __restrict__ w2, const float* __restrict__ w3,
    const float* __restrict__ w4, float* __restrict__ wT)
{
    const float* ws[5] = {w0, w1, w2, w3, w4};
    const float* w = ws[blockIdx.y];
    float* o = wT + blockIdx.y * (3 * CH * 3 * CH);
    int i = blockIdx.x * 256 + threadIdx.x;
    if (i < CH * CH * 9) {
        int kw = i % 3, kh = (i / 3) % 3, ci = (i / 9) % CH, co = i / (9 * CH);
        o[((kh * CH + ci) * 3 + kw) * CH + co] = w[i];
    }
}

// ---------------------------------------------------------------------------
// 3x3 conv (no bias) + fused BN-stats accumulation via atomics
// ---------------------------------------------------------------------------
__global__ void __launch_bounds__(256) conv3x3_stats_kernel(
    const float* __restrict__ in, const float* __restrict__ wT,
    float* __restrict__ out, float* __restrict__ stats)
{
    extern __shared__ float smemf[];
    float* sRow = smemf;
    float* sW   = smemf + 64 * 66;

    const int b   = blockIdx.x >> 6;
    const int h   = blockIdx.x & 63;
    const int tid = threadIdx.x;
    const int cg  = tid >> 4;
    const int pg  = tid & 15;

    ull acc[4][2];
    #pragma unroll
    for (int i = 0; i < 4; ++i) { acc[i][0] = 0ull; acc[i][1] = 0ull; }

    for (int kh = 0; kh < 3; ++kh) {
        const int row = h + kh - 1;
        const float* wsrc = wT + kh * (CH * 3 * CH);
        for (int i = tid; i < CH * 3 * CH; i += 256) sW[i] = wsrc[i];
        if (row >= 0 && row < HW) {
            const float* src = in + (size_t)(b * CH) * NPIX + row * HW;
            for (int i = tid; i < CH * HW; i += 256) {
                int ci = i >> 6, w = i & 63;
                sRow[ci * 66 + 1 + w] = src[(size_t)ci * NPIX + w];
            }
        } else {
            for (int i = tid; i < CH * HW; i += 256) {
                int ci = i >> 6, w = i & 63;
                sRow[ci * 66 + 1 + w] = 0.f;
            }
        }
        if (tid < 64) { sRow[tid * 66] = 0.f; sRow[tid * 66 + 65] = 0.f; }
        __syncthreads();

        #pragma unroll 4
        for (int ci = 0; ci < CH; ++ci) {
            const int rb = ci * 66 + (pg << 1);
            float2 A01 = *(const float2*)&sRow[rb];
            float2 A23 = *(const float2*)&sRow[rb + 2];
            float2 B01 = *(const float2*)&sRow[rb + 32];
            float2 B23 = *(const float2*)&sRow[rb + 34];
            ull pA[3], pB[3];
            pA[0] = pk2(A01.x, A01.y); pA[1] = pk2(A01.y, A23.x); pA[2] = pk2(A23.x, A23.y);
            pB[0] = pk2(B01.x, B01.y); pB[1] = pk2(B01.y, B23.x); pB[2] = pk2(B23.x, B23.y);
            const float* wp = &sW[ci * 192 + (cg << 2)];
            #pragma unroll
            for (int kw = 0; kw < 3; ++kw) {
                float4 wv = *(const float4*)(wp + kw * 64);
                const float wf[4] = {wv.x, wv.y, wv.z, wv.w};
                #pragma unroll
                for (int i = 0; i < 4; ++i) {
                    ull wd = pk2(wf[i], wf[i]);
                    fma2(acc[i][0], wd, pA[kw]);
                    fma2(acc[i][1], wd, pB[kw]);
                }
            }
        }
        __syncthreads();
    }

    const int w0 = pg << 1;
    #pragma unroll
    for (int i = 0; i < 4; ++i) {
        int co = (cg << 2) + i;
        float2 r0 = upk2(acc[i][0]);
        float2 r1 = upk2(acc[i][1]);
        float* o = out + (size_t)(b * CH + co) * NPIX + h * HW;
        *(float2*)&o[w0]      = r0;
        *(float2*)&o[w0 + 32] = r1;
        float sa = r0.x + r0.y + r1.x + r1.y;
        float sq = r0.x * r0.x + r0.y * r0.y + r1.x * r1.x + r1.y * r1.y;
        #pragma unroll
        for (int off = 1; off < 16; off <<= 1) {
            sa += __shfl_xor_sync(0xffffffffu, sa, off);
            sq += __shfl_xor_sync(0xffffffffu, sq, off);
        }
        if (pg == 0) {
            atomicAdd(&stats[co], sa);
            atomicAdd(&stats[CH + co], sq);
        }
    }
}

__global__ void bnfinalize_kernel(const float* __restrict__ stats,
                                  float* __restrict__ mean, float* __restrict__ rstd)
{
    int c = threadIdx.x;
    const float invN = 1.f / (BATCH * NPIX);
    float m = stats[c] * invN;
    float v = stats[CH + c] * invN - m * m;
    mean[c] = m;
    rstd[c] = rsqrtf(v + EPSBN);
}

// BN apply + ReLU (final output only)
__global__ void __launch_bounds__(256) bnapply_kernel(
    const float* __restrict__ v, const float* __restrict__ mean,
    const float* __restrict__ rstd, const float* __restrict__ gamma,
    const float* __restrict__ beta, float* __restrict__ out)
{
    int i = blockIdx.x * 256 + threadIdx.x;
    int c = (i >> 12) & 63;
    float r = (v[i] - mean[c]) * rstd[c] * gamma[c] + beta[c];
    out[i] = fmaxf(r, 0.f);
}

// ---------------------------------------------------------------------------
// Fused projection conv: 3 weight sets (theta, phi, g) over the SAME input,
// BN+ReLU applied on input load, epilogue writes bf16 hi/lo operands in
// final layouts (theta/phi transposed to [b][n][c], g direct [b][c][m]).
// smem: sRow 16896B | sW 49152B (sT 64x65 overlaps sW in epilogue) | sBN 512B
// ---------------------------------------------------------------------------
__global__ void __launch_bounds__(256) conv3x3_proj_kernel(
    const float* __restrict__ c1, const float* __restrict__ wT3,
    const float* __restrict__ mean, const float* __restrict__ rstd,
    const float* __restrict__ gamma, const float* __restrict__ beta,
    const float* __restrict__ thb, const float* __restrict__ phb,
    const float* __restrict__ gbias,
    __nv_bfloat16* __restrict__ thH, __nv_bfloat16* __restrict__ thL,
    __nv_bfloat16* __restrict__ phH, __nv_bfloat16* __restrict__ phL,
    __nv_bfloat16* __restrict__ gH,  __nv_bfloat16* __restrict__ gL)
{
    extern __shared__ float smemf[];
    float* sRow   = smemf;                       // 64*66
    float* sW     = smemf + 64 * 66;             // 12288 floats
    float* sScale = smemf + 64 * 66 + 12288;     // 64
    float* sShift = sScale + 64;                 // 64

    const int b   = blockIdx.x >> 6;
    const int h   = blockIdx.x & 63;
    const int tid = threadIdx.x;
    const int cg  = tid >> 4;
    const int pg  = tid & 15;

    if (tid < 64) {
        float sc = rstd[tid] * gamma[tid];
        sScale[tid] = sc;
        sShift[tid] = beta[tid] - mean[tid] * sc;
    }

    ull acc[3][4][2];
    #pragma unroll
    for (int s = 0; s < 3; ++s)
        #pragma unroll
        for (int i = 0; i < 4; ++i) { acc[s][i][0] = 0ull; acc[s][i][1] = 0ull; }

    for (int kh = 0; kh < 3; ++kh) {
        const int row = h + kh - 1;
        __syncthreads();      // prev compute done (covers sRow & sScale first use)
        if (row >= 0 && row < HW) {
            const float* src = c1 + (size_t)(b * CH) * NPIX + row * HW;
            for (int i = tid; i < CH * HW; i += 256) {
                int ci = i >> 6, w = i & 63;
                float v = src[(size_t)ci * NPIX + w];
                sRow[ci * 66 + 1 + w] = fmaxf(fmaf(v, sScale[ci], sShift[ci]), 0.f);
            }
        } else {
            for (int i = tid; i < CH * HW; i += 256) {
                int ci = i >> 6, w = i & 63;
                sRow[ci * 66 + 1 + w] = 0.f;
            }
        }
        if (tid < 64) { sRow[tid * 66] = 0.f; sRow[tid * 66 + 65] = 0.f; }

        for (int s = 0; s < 3; ++s) {
            __syncthreads();
            const float* wsrc = wT3 + s * (3 * CH * 3 * CH) + kh * (CH * 3 * CH);
            for (int i = tid; i < CH * 3 * CH; i += 256) sW[i] = wsrc[i];
            __syncthreads();

            #pragma unroll 4
            for (int ci = 0; ci < CH; ++ci) {
                const int rb = ci * 66 + (pg << 1);
                float2 A01 = *(const float2*)&sRow[rb];
                float2 A23 = *(const float2*)&sRow[rb + 2];
                float2 B01 = *(const float2*)&sRow[rb + 32];
                float2 B23 = *(const float2*)&sRow[rb + 34];
                ull pA[3], pB[3];
                pA[0] = pk2(A01.x, A01.y); pA[1] = pk2(A01.y, A23.x); pA[2] = pk2(A23.x, A23.y);
                pB[0] = pk2(B01.x, B01.y); pB[1] = pk2(B01.y, B23.x); pB[2] = pk2(B23.x, B23.y);
                const float* wp = &sW[ci * 192 + (cg << 2)];
                #pragma unroll
                for (int kw = 0; kw < 3; ++kw) {
                    float4 wv = *(const float4*)(wp + kw * 64);
                    const float wf[4] = {wv.x, wv.y, wv.z, wv.w};
                    #pragma unroll
                    for (int i = 0; i < 4; ++i) {
                        ull wd = pk2(wf[i], wf[i]);
                        fma2(acc[s][i][0], wd, pA[kw]);
                        fma2(acc[s][i][1], wd, pB[kw]);
                    }
                }
            }
        }
    }
    __syncthreads();

    const int w0 = pg << 1;

    // ---- g: direct [b][c][m] bf16 hi/lo ----
    #pragma unroll
    for (int i = 0; i < 4; ++i) {
        int co = (cg << 2) + i;
        float bv = gbias[co];
        float2 r0 = upk2(acc[2][i][0]); r0.x += bv; r0.y += bv;
        float2 r1 = upk2(acc[2][i][1]); r1.x += bv; r1.y += bv;
        __nv_bfloat16 h0 = __float2bfloat16_rn(r0.x), h1 = __float2bfloat16_rn(r0.y);
        __nv_bfloat16 h2 = __float2bfloat16_rn(r1.x), h3 = __float2bfloat16_rn(r1.y);
        __nv_bfloat16 l0 = __float2bfloat16_rn(r0.x - __bfloat162float(h0));
        __nv_bfloat16 l1 = __float2bfloat16_rn(r0.y - __bfloat162float(h1));
        __nv_bfloat16 l2 = __float2bfloat16_rn(r1.x - __bfloat162float(h2));
        __nv_bfloat16 l3 = __float2bfloat16_rn(r1.y - __bfloat162float(h3));
        size_t base = ((size_t)(b * CH + co) << 12) + h * 64;
        __nv_bfloat162 p;
        p.x = h0; p.y = h1; *(__nv_bfloat162*)&gH[base + w0]      = p;
        p.x = h2; p.y = h3; *(__nv_bfloat162*)&gH[base + w0 + 32] = p;
        p.x = l0; p.y = l1; *(__nv_bfloat162*)&gL[base + w0]      = p;
        p.x = l2; p.y = l3; *(__nv_bfloat162*)&gL[base + w0 + 32] = p;
    }

    // ---- theta / phi: transpose to [b][n][c] bf16 hi/lo ----
    float* sT = sW;   // 64 x 65, weights dead
    #pragma unroll
    for (int s = 0; s < 2; ++s) {
        const float* bias = s ? phb : thb;
        __syncthreads();
        #pragma unroll
        for (int i = 0; i < 4; ++i) {
            int co = (cg << 2) + i;
            float bv = bias[co];
            float2 r0 = upk2(acc[s][i][0]);
            float2 r1 = upk2(acc[s][i][1]);
            sT[(w0)      * 65 + co] = r0.x + bv;
            sT[(w0 + 1)  * 65 + co] = r0.y + bv;
            sT[(w0 + 32) * 65 + co] = r1.x + bv;
            sT[(w0 + 33) * 65 + co] = r1.y + bv;
        }
        __syncthreads();
        __nv_bfloat16* H = s ? phH : thH;
        __nv_bfloat16* L = s ? phL : thL;
        const int n = tid >> 2, cs = (tid & 3) * 16;
        size_t rowbase = ((size_t)b * NPIX + h * 64 + n) * 64 + cs;
        __nv_bfloat16 hv[16], lv[16];
        #pragma unroll
        for (int k = 0; k < 16; ++k) {
            float v = sT[n * 65 + cs + k];
            hv[k] = __float2bfloat16_rn(v);
            lv[k] = __float2bfloat16_rn(v - __bfloat162float(hv[k]));
        }
        *(uint4*)&H[rowbase]     = ((uint4*)hv)[0];
        *(uint4*)&H[rowbase + 8] = ((uint4*)hv)[1];
        *(uint4*)&L[rowbase]     = ((uint4*)lv)[0];
        *(uint4*)&L[rowbase + 8] = ((uint4*)lv)[1];
    }
}

// ---------------------------------------------------------------------------
// Fused attention + 1x1 W conv + residual -> z
// Mainloop identical to R8. Epilogue: y (scaled, transposed in smem) is fed
// through z = Ww @ y + Wb + x in-kernel (f32x2 matvec over smem), then stored.
// ---------------------------------------------------------------------------
#define FA_TH_HI 0
#define FA_TH_LO 16384
#define FA_BUF0  32768
#define FA_BUF1  98304
#define FA_PH    0
#define FA_PL    16384
#define FA_GH    32768
#define FA_GL    49152
#define FA_P     163840
#define FA_RS    196608
#define FA_SMEM  197120
// epilogue overlays (all below 98304, buffers dead):
#define EP_SY    0          // 128 x 65 f32 = 33280
#define EP_SW    36864      // 64 x 65 f32  = 16640
#define EP_SB    53504      // 64 f32
#define EP_SZ    57344      // 128 x 65 f32 = 33280

__global__ void __launch_bounds__(256, 1) attn_fused_kernel(
    const __nv_bfloat16* __restrict__ thT_hi, const __nv_bfloat16* __restrict__ thT_lo,
    const __nv_bfloat16* __restrict__ phT_hi, const __nv_bfloat16* __restrict__ phT_lo,
    const __nv_bfloat16* __restrict__ g_hi,   const __nv_bfloat16* __restrict__ g_lo,
    const float* __restrict__ Ww, const float* __restrict__ Wb,
    const float* __restrict__ x, float* __restrict__ z)
{
    extern __shared__ __align__(128) char smem[];
    const uint32_t sb = smem_u32(smem);
    const int tid = threadIdx.x, w = tid >> 5, lane = tid & 31;
    const int n0 = blockIdx.x * 128, b = blockIdx.y;
    const int wn = w & 3, wm = w >> 2;

    float* sRS = (float*)(smem + FA_RS);
    if (tid < 128) sRS[tid] = 0.f;

    {
        const uint4* Ah = (const uint4*)(thT_hi + ((size_t)b * NPIX + n0) * 64);
        const uint4* Al = (const uint4*)(thT_lo + ((size_t)b * NPIX + n0) * 64);
        for (int i = tid; i < 1024; i += 256) {
            uint32_t off = SW128((uint32_t)(i >> 3) * 128 + (i & 7) * 16);
            *(uint4*)(smem + FA_TH_HI + off) = Ah[i];
            *(uint4*)(smem + FA_TH_LO + off) = Al[i];
        }
    }

    const char* phh = (const char*)(phT_hi + (size_t)b * NPIX * 64);
    const char* phl = (const char*)(phT_lo + (size_t)b * NPIX * 64);

    auto load_chunk = [&](int mb, uint32_t buf) {
        const char* ph = phh + (size_t)mb * 128;
        const char* pl = phl + (size_t)mb * 128;
        for (int i = tid; i < 1024; i += 256) {
            uint32_t off = SW128((uint32_t)(i >> 3) * 128 + (i & 7) * 16);
            cpasync16(sb + buf + FA_PH + off, ph + i * 16);
            cpasync16(sb + buf + FA_PL + off, pl + i * 16);
        }
        for (int i = tid; i < 1024; i += 256) {
            int row = i >> 4, seg = i & 15;
            uint32_t off = (uint32_t)(seg >> 3) * 8192 + SW128((uint32_t)row * 128 + (seg & 7) * 16);
            const size_t go = ((size_t)(b * CH + row)) * NPIX + mb + seg * 8;
            cpasync16(sb + buf + FA_GH + off, g_hi + go);
            cpasync16(sb + buf + FA_GL + off, g_lo + go);
        }
        cpasync_commit();
    };

    load_chunk(0, FA_BUF0);
    cpasync_wait0();
    __syncthreads();

    float acco[2][4][4];
    #pragma unroll
    for (int i = 0; i < 2; ++i)
        #pragma unroll
        for (int j = 0; j < 4; ++j)
            #pragma unroll
            for (int k = 0; k < 4; ++k) acco[i][j][k] = 0.f;
    float rs[2][2] = {{0.f, 0.f}, {0.f, 0.f}};

    const int arow = (lane & 15), acol = (lane >> 4);
    const int brow = ((lane >> 4) << 3) + (lane & 7), bcol = ((lane >> 3) & 1);

    for (int c = 0; c < 32; ++c) {
        const uint32_t buf  = (c & 1) ? FA_BUF1 : FA_BUF0;
        const uint32_t nbuf = (c & 1) ? FA_BUF0 : FA_BUF1;
        if (c < 31) load_chunk((c + 1) * 128, nbuf);

        float accs[2][8][4];
        #pragma unroll
        for (int i = 0; i < 2; ++i)
            #pragma unroll
            for (int j = 0; j < 8; ++j)
                #pragma unroll
                for (int k = 0; k < 4; ++k) accs[i][j][k] = 0.f;

        #pragma unroll
        for (int k = 0; k < 4; ++k) {
            uint32_t aH[2][4], aL[2][4], bH[4][4], bL[4][4];
            #pragma unroll
            for (int fi = 0; fi < 2; ++fi) {
                uint32_t off = SW128((uint32_t)(wn * 32 + fi * 16 + arow) * 128 + (k * 2 + acol) * 16);
                ldsm4(aH[fi], sb + FA_TH_HI + off);
                ldsm4(aL[fi], sb + FA_TH_LO + off);
            }
            #pragma unroll
            for (int q = 0; q < 4; ++q) {
                uint32_t off = SW128((uint32_t)(wm * 64 + q * 16 + brow) * 128 + (k * 2 + bcol) * 16);
                ldsm4(bH[q], sb + buf + FA_PH + off);
                ldsm4(bL[q], sb + buf + FA_PL + off);
            }
            #pragma unroll
            for (int fi = 0; fi < 2; ++fi)
                #pragma unroll
                for (int q = 0; q < 4; ++q) {
                    mma16816(accs[fi][2 * q],     aH[fi], &bH[q][0]);
                    mma16816(accs[fi][2 * q + 1], aH[fi], &bH[q][2]);
                    mma16816(accs[fi][2 * q],     aH[fi], &bL[q][0]);
                    mma16816(accs[fi][2 * q + 1], aH[fi], &bL[q][2]);
                    mma16816(accs[fi][2 * q],     aL[fi], &bH[q][0]);
                    mma16816(accs[fi][2 * q + 1], aL[fi], &bH[q][2]);
                }
        }

        #pragma unroll
        for (int fi = 0; fi < 2; ++fi) {
            const int n1 = wn * 32 + fi * 16 + (lane >> 2);
            #pragma unroll
            for (int bj = 0; bj < 8; ++bj) {
                const int ml = wm * 64 + bj * 8 + (lane & 3) * 2;
                const uint32_t pan = (uint32_t)(ml >> 6) * 16384;
                const int col = ml & 63;
                float e0 = __expf(accs[fi][bj][0]);
                float e1 = __expf(accs[fi][bj][1]);
                float e2 = __expf(accs[fi][bj][2]);
                float e3 = __expf(accs[fi][bj][3]);
                rs[fi][0] += e0 + e1; rs[fi][1] += e2 + e3;
                __nv_bfloat162 p01 = __floats2bfloat162_rn(e0, e1);
                __nv_bfloat162 p23 = __floats2bfloat162_rn(e2, e3);
                *(uint32_t*)(smem + FA_P + pan + SW128((uint32_t)n1 * 128 + col * 2))       = *(uint32_t*)&p01;
                *(uint32_t*)(smem + FA_P + pan + SW128((uint32_t)(n1 + 8) * 128 + col * 2)) = *(uint32_t*)&p23;
            }
        }
        __syncthreads();

        #pragma unroll
        for (int kk = 0; kk < 8; ++kk) {
            const uint32_t panA = (uint32_t)(kk >> 2) * 16384;
            const uint32_t panB = (uint32_t)(kk >> 2) * 8192;
            const int kc = kk & 3;
            uint32_t aP[2][4], bH[2][4], bL[2][4];
            #pragma unroll
            for (int fi = 0; fi < 2; ++fi) {
                uint32_t off = SW128((uint32_t)(wn * 32 + fi * 16 + arow) * 128 + (kc * 2 + acol) * 16);
                ldsm4(aP[fi], sb + FA_P + panA + off);
            }
            #pragma unroll
            for (int q = 0; q < 2; ++q) {
                uint32_t off = SW128((uint32_t)(wm * 32 + q * 16 + brow) * 128 + (kc * 2 + bcol) * 16);
                ldsm4(bH[q], sb + buf + FA_GH + panB + off);
                ldsm4(bL[q], sb + buf + FA_GL + panB + off);
            }
            #pragma unroll
            for (int fi = 0; fi < 2; ++fi)
                #pragma unroll
                for (int q = 0; q < 2; ++q) {
                    mma16816(acco[fi][2 * q],     aP[fi], &bH[q][0]);
                    mma16816(acco[fi][2 * q + 1], aP[fi], &bH[q][2]);
                    mma16816(acco[fi][2 * q],     aP[fi], &bL[q][0]);
                    mma16816(acco[fi][2 * q + 1], aP[fi], &bL[q][2]);
                }
        }

        cpasync_wait0();
        __syncthreads();
    }

    // ---- rowsum reduce ----
    #pragma unroll
    for (int fi = 0; fi < 2; ++fi) {
        const int n1 = wn * 32 + fi * 16 + (lane >> 2);
        float s1 = rs[fi][0], s2 = rs[fi][1];
        s1 += __shfl_xor_sync(0xffffffffu, s1, 1);
        s1 += __shfl_xor_sync(0xffffffffu, s1, 2);
        s2 += __shfl_xor_sync(0xffffffffu, s2, 1);
        s2 += __shfl_xor_sync(0xffffffffu, s2, 2);
        if ((lane & 3) == 0) {
            atomicAdd(&sRS[n1], s1);
            atomicAdd(&sRS[n1 + 8], s2);
        }
    }
    __syncthreads();

    // ---- part A: scale + transpose y into sY ----
    float inv[2][2];
    #pragma unroll
    for (int fi = 0; fi < 2; ++fi) {
        int n1 = wn * 32 + fi * 16 + (lane >> 2);
        inv[fi][0] = 1.f / sRS[n1];
        inv[fi][1] = 1.f / sRS[n1 + 8];
    }
    float* sY = (float*)(smem + EP_SY);
    #pragma unroll
    for (int fi = 0; fi < 2; ++fi) {
        int n1 = wn * 32 + fi * 16 + (lane >> 2);
        #pragma unroll
        for (int bj = 0; bj < 4; ++bj) {
            int cl = wm * 32 + bj * 8 + (lane & 3) * 2;
            sY[n1 * 65 + cl]           = acco[fi][bj][0] * inv[fi][0];
            sY[n1 * 65 + cl + 1]       = acco[fi][bj][1] * inv[fi][0];
            sY[(n1 + 8) * 65 + cl]     = acco[fi][bj][2] * inv[fi][1];
            sY[(n1 + 8) * 65 + cl + 1] = acco[fi][bj][3] * inv[fi][1];
        }
    }
    // load W (1x1 conv) while sY fills
    float* sWm = (float*)(smem + EP_SW);   // [co][ci], stride 65
    float* sBv = (float*)(smem + EP_SB);
    for (int i = tid; i < 4096; i += 256) sWm[(i >> 6) * 65 + (i & 63)] = Ww[i];
    if (tid < 64) sBv[tid] = Wb[tid];
    __syncthreads();

    // ---- part B: z = Ww @ y + Wb (matvec over smem, f32x2 on n-pairs) ----
    float* sZ = (float*)(smem + EP_SZ);
    {
        const int nb = (tid >> 3) * 4;     // 4 consecutive n
        const int cb = (tid & 7) * 8;      // 8 consecutive co
        ull a2[8][2];
        #pragma unroll
        for (int j = 0; j < 8; ++j) { a2[j][0] = 0ull; a2[j][1] = 0ull; }
        #pragma unroll 8
        for (int ci = 0; ci < 64; ++ci) {
            ull y01 = pk2(sY[nb * 65 + ci],       sY[(nb + 1) * 65 + ci]);
            ull y23 = pk2(sY[(nb + 2) * 65 + ci], sY[(nb + 3) * 65 + ci]);
            #pragma unroll
            for (int j = 0; j < 8; ++j) {
                float wv = sWm[(cb + j) * 65 + ci];
                ull wd = pk2(wv, wv);
                fma2(a2[j][0], wd, y01);
                fma2(a2[j][1], wd, y23);
            }
        }
        #pragma unroll
        for (int j = 0; j < 8; ++j) {
            float bv = sBv[cb + j];
            float2 v01 = upk2(a2[j][0]);
            float2 v23 = upk2(a2[j][1]);
            sZ[nb * 65 + cb + j]       = v01.x + bv;
            sZ[(nb + 1) * 65 + cb + j] = v01.y + bv;
            sZ[(nb + 2) * 65 + cb + j] = v23.x + bv;
            sZ[(nb + 3) * 65 + cb + j] = v23.y + bv;
        }
    }
    __syncthreads();

    // ---- store z with residual (coalesced) ----
    for (int i = tid; i < 8192; i += 256) {
        int c = i >> 7, n = i & 127;
        size_t o = ((size_t)(b * CH + c) << 12) + n0 + n;
        z[o] = sZ[n * 65 + c] + x[o];
    }
}

// ---------------------------------------------------------------------------
// Launch
// ---------------------------------------------------------------------------
extern "C" void kernel_launch(void* const* d_in, const int* in_sizes, int n_in,
                              void* d_out, int out_size)
{
    const float* x       = (const float*)d_in[0];
    const float* conv1_w = (const float*)d_in[1];
    const float* bn1_g   = (const float*)d_in[2];
    const float* bn1_b   = (const float*)d_in[3];
    const float* theta_w = (const float*)d_in[4];
    const float* theta_b = (const float*)d_in[5];
    const float* phi_w   = (const float*)d_in[6];
    const float* phi_b   = (const float*)d_in[7];
    const float* gw      = (const float*)d_in[8];
    const float* gb      = (const float*)d_in[9];
    const float* W_w     = (const float*)d_in[10];
    const float* W_b     = (const float*)d_in[11];
    const float* conv2_w = (const float*)d_in[12];
    const float* bn2_g   = (const float*)d_in[13];
    const float* bn2_b   = (const float*)d_in[14];
    float* out = (float*)d_out;

    float *p_c1, *p_z, *p_mean, *p_rstd, *p_stats, *p_wT;
    __nv_bfloat16 *p_thH, *p_thL, *p_phH, *p_phL, *p_gH, *p_gL;
    cudaGetSymbolAddress((void**)&p_c1,   g_c1raw);
    cudaGetSymbolAddress((void**)&p_z,    g_z);
    cudaGetSymbolAddress((void**)&p_mean, g_mean);
    cudaGetSymbolAddress((void**)&p_rstd, g_rstd);
    cudaGetSymbolAddress((void**)&p_stats, g_stats);
    cudaGetSymbolAddress((void**)&p_wT,   g_wT);
    cudaGetSymbolAddress((void**)&p_thH,  g_thT_hi);
    cudaGetSymbolAddress((void**)&p_thL,  g_thT_lo);
    cudaGetSymbolAddress((void**)&p_phH,  g_phT_hi);
    cudaGetSymbolAddress((void**)&p_phL,  g_phT_lo);
    cudaGetSymbolAddress((void**)&p_gH,   g_g_hi);
    cudaGetSymbolAddress((void**)&p_gL,   g_g_lo);

    const int WSZ = 3 * CH * 3 * CH;
    const int CONV_SMEM = (64 * 66 + CH * 3 * CH) * (int)sizeof(float);          // 66048
    const int PROJ_SMEM = (64 * 66 + CH * 3 * CH + 128) * (int)sizeof(float);    // 66560
    cudaFuncSetAttribute(conv3x3_stats_kernel, cudaFuncAttributeMaxDynamicSharedMemorySize, CONV_SMEM);
    cudaFuncSetAttribute(conv3x3_proj_kernel,  cudaFuncAttributeMaxDynamicSharedMemorySize, PROJ_SMEM);
    cudaFuncSetAttribute(attn_fused_kernel,    cudaFuncAttributeMaxDynamicSharedMemorySize, FA_SMEM);

    wtrans_all_kernel<<<dim3(144, 5), 256>>>(conv1_w, theta_w, phi_w, gw, conv2_w, p_wT);

    // conv1 (+BN1 stats)
    cudaMemsetAsync(p_stats, 0, 2 * CH * sizeof(float));
    conv3x3_stats_kernel<<<BATCH * HW, 256, CONV_SMEM>>>(x, p_wT + 0 * WSZ, p_c1, p_stats);
    bnfinalize_kernel<<<1, 64>>>(p_stats, p_mean, p_rstd);

    // fused projections (BN1 applied on load; direct bf16 hi/lo outputs)
    conv3x3_proj_kernel<<<BATCH * HW, 256, PROJ_SMEM>>>(
        p_c1, p_wT + 1 * WSZ, p_mean, p_rstd, bn1_g, bn1_b,
        theta_b, phi_b, gb, p_thH, p_thL, p_phH, p_phL, p_gH, p_gL);

    // fused attention + 1x1 W conv + residual -> z
    attn_fused_kernel<<<dim3(32, BATCH), 256, FA_SMEM>>>(
        p_thH, p_thL, p_phH, p_phL, p_gH, p_gL, W_w, W_b, x, p_z);

    // conv2 (+BN2 stats) + final BN apply
    cudaMemsetAsync(p_stats, 0, 2 * CH * sizeof(float));
    conv3x3_stats_kernel<<<BATCH * HW, 256, CONV_SMEM>>>(p_z, p_wT + 4 * WSZ, p_c1, p_stats);
    bnfinalize_kernel<<<1, 64>>>(p_stats, p_mean, p_rstd);
    bnapply_kernel<<<(BATCH * CH * NPIX) / 256, 256>>>(p_c1, p_mean, p_rstd, bn2_g, bn2_b, out);
}

// round 11
// speedup vs baseline: 5.2218x; 1.3932x over previous
#include <cuda_runtime.h>
#include <cuda_bf16.h>
#include <cstdint>

typedef unsigned long long ull;

#define BATCH 4
#define CH    64
#define HW    64
#define NPIX  4096
#define EPSBN 1e-5f

// ---------------------------------------------------------------------------
// Scratch
// ---------------------------------------------------------------------------
__device__ float g_c1raw[BATCH * CH * NPIX];
__device__ float g_z    [BATCH * CH * NPIX];
__device__ float g_mean[CH];
__device__ float g_rstd[CH];
__device__ float g_stats[2 * CH];
__device__ __nv_bfloat16 g_wmma[5 * 9 * 2 * CH * CH];   // [set][tap][hi/lo][co][ci]

// bf16 operands for mma.sync
__device__ __nv_bfloat16 g_thT_hi[BATCH * NPIX * CH];   // [b][n][c]
__device__ __nv_bfloat16 g_thT_lo[BATCH * NPIX * CH];
__device__ __nv_bfloat16 g_phT_hi[BATCH * NPIX * CH];   // [b][m][c]
__device__ __nv_bfloat16 g_phT_lo[BATCH * NPIX * CH];
__device__ __nv_bfloat16 g_g_hi [BATCH * CH * NPIX];    // [b][c][m]
__device__ __nv_bfloat16 g_g_lo [BATCH * CH * NPIX];

// ---------------------------------------------------------------------------
// f32x2 helpers
// ---------------------------------------------------------------------------
__device__ __forceinline__ ull pk2(float lo, float hi) {
    ull r; asm("mov.b64 %0, {%1, %2};" : "=l"(r) : "f"(lo), "f"(hi)); return r;
}
__device__ __forceinline__ void fma2(ull& d, ull a, ull b) {
    asm("fma.rn.f32x2 %0, %1, %2, %0;" : "+l"(d) : "l"(a), "l"(b));
}
__device__ __forceinline__ float2 upk2(ull v) {
    float2 r; asm("mov.b64 {%0, %1}, %2;" : "=f"(r.x), "=f"(r.y) : "l"(v)); return r;
}

// ---------------------------------------------------------------------------
// mma.sync / cp.async helpers
// ---------------------------------------------------------------------------
__device__ __forceinline__ uint32_t smem_u32(const void* p) {
    uint32_t a;
    asm("{ .reg .u64 t; cvta.to.shared.u64 t, %1; cvt.u32.u64 %0, t; }" : "=r"(a) : "l"(p));
    return a;
}
#define SW128(o) ((o) ^ ((((uint32_t)(o)) >> 3) & 0x70))

__device__ __forceinline__ void ldsm4(uint32_t* r, uint32_t addr) {
    asm volatile("ldmatrix.sync.aligned.m8n8.x4.shared.b16 {%0,%1,%2,%3}, [%4];"
        : "=r"(r[0]), "=r"(r[1]), "=r"(r[2]), "=r"(r[3]) : "r"(addr));
}
__device__ __forceinline__ void mma16816(float* d, const uint32_t* a, const uint32_t* b) {
    asm volatile("mma.sync.aligned.m16n8k16.row.col.f32.bf16.bf16.f32 "
        "{%0,%1,%2,%3},{%4,%5,%6,%7},{%8,%9},{%0,%1,%2,%3};"
        : "+f"(d[0]), "+f"(d[1]), "+f"(d[2]), "+f"(d[3])
        : "r"(a[0]), "r"(a[1]), "r"(a[2]), "r"(a[3]), "r"(b[0]), "r"(b[1]));
}
__device__ __forceinline__ void cpasync16(uint32_t dst, const void* src) {
    asm volatile("cp.async.cg.shared.global [%0], [%1], 16;" :: "r"(dst), "l"(src));
}
__device__ __forceinline__ void cpasync_commit() {
    asm volatile("cp.async.commit_group;" ::: "memory");
}
__device__ __forceinline__ void cpasync_wait0() {
    asm volatile("cp.async.wait_group 0;" ::: "memory");
}

// ---------------------------------------------------------------------------
// Weight prep: w[co][ci][kh][kw] fp32 -> [set][tap][hi/lo][co][ci] bf16
// ---------------------------------------------------------------------------
__global__ void wtrans_mma_kernel(
    const float* __restrict__ w0, const float* __restrict__ w1,
    const float* __restrict__ w2, const float* __restrict__ w3,
    const float* __restrict__ w4, __nv_bfloat16* __restrict__ wm)
{
    const float* ws[5] = {w0, w1, w2, w3, w4};
    int i = blockIdx.x * 256 + threadIdx.x;      // over 5*9*4096
    if (i < 5 * 9 * 4096) {
        int set = i / 36864, rem = i % 36864;
        int tap = rem / 4096, rem2 = rem % 4096;
        int co = rem2 >> 6, ci = rem2 & 63;
        int kh = tap / 3, kw = tap % 3;
        float v = ws[set][co * 576 + ci * 9 + kh * 3 + kw];
        __nv_bfloat16 h = __float2bfloat16_rn(v);
        __nv_bfloat16 l = __float2bfloat16_rn(v - __bfloat162float(h));
        size_t base = ((size_t)(set * 9 + tap) * 2) * 4096 + co * 64 + ci;
        wm[base] = h;
        wm[base + 4096] = l;
    }
}

// ---------------------------------------------------------------------------
// HMMA implicit-GEMM 3x3 conv.
// MODE 0: 1 weight set, fp32 out + fused BN stats (atomics).
// MODE 1: 3 sets (theta,phi,g) over BN+ReLU'd input; bf16 hi/lo outputs.
// Block = (b, 2 output rows) = 128 pixels x 64 co. 8 warps: w&1 -> co half,
// w>>1 -> pixel quarter. K = 64ci x 9 taps, bf16 hi/lo 3-pass.
// smem: sXT hi/lo (transposed input, stride 72) | 2x weight bufs | sOut | BN
// ---------------------------------------------------------------------------
#define SXT_HI 0
#define SXT_LO 38016
#define SWB0   76032
#define SWB1   94464
#define SOUT   112896
#define SBN    146688
#define CV_SMEM0 112896
#define CV_SMEM1 147200

template<int MODE>
__global__ void __launch_bounds__(256, 1) conv_mma_kernel(
    const float* __restrict__ in, const __nv_bfloat16* __restrict__ wm,
    float* __restrict__ out, float* __restrict__ stats,
    const float* __restrict__ mean, const float* __restrict__ rstd,
    const float* __restrict__ gamma, const float* __restrict__ beta,
    const float* __restrict__ thb, const float* __restrict__ phb,
    const float* __restrict__ gbias,
    __nv_bfloat16* __restrict__ thH, __nv_bfloat16* __restrict__ thL,
    __nv_bfloat16* __restrict__ phH, __nv_bfloat16* __restrict__ phL,
    __nv_bfloat16* __restrict__ gH,  __nv_bfloat16* __restrict__ gL)
{
    extern __shared__ __align__(128) char smem[];
    const uint32_t sb = smem_u32(smem);
    const int tid = threadIdx.x, w = tid >> 5, lane = tid & 31;
    const int h0 = blockIdx.x * 2;
    const int b  = blockIdx.y;
    const int mpair = w & 1, nq = w >> 1;
    const int co_base = mpair * 32;

    if (MODE == 1) {
        if (tid < 64) {
            float sc = rstd[tid] * gamma[tid];
            ((float*)(smem + SBN))[tid]      = sc;
            ((float*)(smem + SBN))[64 + tid] = beta[tid] - mean[tid] * sc;
        }
        __syncthreads();
    }

    // ---- stage transposed hi/lo input rows h0-1 .. h0+2 ----
    {
        const float* scl = (const float*)(smem + SBN);
        const float* shf = scl + 64;
        for (int i = tid; i < 512; i += 256) {
            int r = i >> 7, ci = (i >> 1) & 63, e = i & 1;
            uint32_t off = (uint32_t)((r * 66 + (e ? 65 : 0)) * 72 + ci) * 2;
            *(__nv_bfloat16*)(smem + SXT_HI + off) = __float2bfloat16_rn(0.f);
            *(__nv_bfloat16*)(smem + SXT_LO + off) = __float2bfloat16_rn(0.f);
        }
        #pragma unroll
        for (int j = 0; j < 16; ++j) {
            int e4 = tid + 256 * j;
            int w4 = (e4 & 15) * 4;
            int ci = (e4 >> 4) & 63;
            int ri = e4 >> 10;
            int row = h0 - 1 + ri;
            float4 v = make_float4(0.f, 0.f, 0.f, 0.f);
            if (row >= 0 && row < HW) {
                v = *(const float4*)&in[((size_t)(b * CH + ci) << 12) + row * HW + w4];
                if (MODE == 1) {
                    float s = scl[ci], t = shf[ci];
                    v.x = fmaxf(fmaf(v.x, s, t), 0.f);
                    v.y = fmaxf(fmaf(v.y, s, t), 0.f);
                    v.z = fmaxf(fmaf(v.z, s, t), 0.f);
                    v.w = fmaxf(fmaf(v.w, s, t), 0.f);
                }
            }
            const float vv[4] = {v.x, v.y, v.z, v.w};
            #pragma unroll
            for (int jj = 0; jj < 4; ++jj) {
                uint32_t off = (uint32_t)((ri * 66 + w4 + jj + 1) * 72 + ci) * 2;
                __nv_bfloat16 h = __float2bfloat16_rn(vv[jj]);
                *(__nv_bfloat16*)(smem + SXT_HI + off) = h;
                *(__nv_bfloat16*)(smem + SXT_LO + off) =
                    __float2bfloat16_rn(vv[jj] - __bfloat162float(h));
            }
        }
    }

    // weight tap load (double-buffered cp.async)
    const int side = tid >> 7, wco = (tid >> 1) & 63, half = tid & 1;
    auto load_w = [&](int q, int buf) {
        const __nv_bfloat16* s = wm + (size_t)q * 8192 + side * 4096 + wco * 64 + half * 32;
        uint32_t d = sb + (buf ? SWB1 : SWB0) + side * 9216 + (uint32_t)(wco * 72 + half * 32) * 2;
        #pragma unroll
        for (int j = 0; j < 4; ++j) cpasync16(d + j * 16, s + j * 8);
        cpasync_commit();
    };

    // lane decodes
    const int bci  = (lane & 3) * 4;          // ci-pair byte offset
    const int bwn  = lane >> 2;               // pixel offset within n-tile
    const int arow = ((lane & 8) ? 8 : 0) + (lane & 7);
    const int acolh = (lane & 16) ? 8 : 0;

    const int NSETS = (MODE == 1) ? 3 : 1;
    const int NT = NSETS * 9;
    load_w(0, 0);
    int q = 0;

    for (int s = 0; s < NSETS; ++s) {
        float acc[2][4][4];
        #pragma unroll
        for (int mi = 0; mi < 2; ++mi)
            #pragma unroll
            for (int nt = 0; nt < 4; ++nt)
                #pragma unroll
                for (int k = 0; k < 4; ++k) acc[mi][nt][k] = 0.f;

        for (int tap = 0; tap < 9; ++tap) {
            cpasync_wait0();
            __syncthreads();
            if (q + 1 < NT) load_w(q + 1, (q + 1) & 1);

            const int dh = tap / 3, dw = tap % 3;
            const uint32_t swb = sb + ((q & 1) ? SWB1 : SWB0);
            int bb[4];
            #pragma unroll
            for (int nt = 0; nt < 4; ++nt) {
                int p0 = nq * 32 + nt * 8;
                int r = (p0 >> 6) + dh;
                int wc = (p0 & 63) + bwn + dw;
                bb[nt] = (r * 66 + wc) * 144 + bci;
            }
            #pragma unroll
            for (int k = 0; k < 4; ++k) {
                uint32_t Ah[2][4], Al[2][4];
                #pragma unroll
                for (int mi = 0; mi < 2; ++mi) {
                    uint32_t ao = (uint32_t)((co_base + mi * 16 + arow) * 72 + k * 16 + acolh) * 2;
                    ldsm4(Ah[mi], swb + ao);
                    ldsm4(Al[mi], swb + 9216 + ao);
                }
                #pragma unroll
                for (int nt = 0; nt < 4; ++nt) {
                    int o = bb[nt] + k * 32;
                    uint32_t bh[2], bl[2];
                    bh[0] = *(const uint32_t*)(smem + SXT_HI + o);
                    bh[1] = *(const uint32_t*)(smem + SXT_HI + o + 16);
                    bl[0] = *(const uint32_t*)(smem + SXT_LO + o);
                    bl[1] = *(const uint32_t*)(smem + SXT_LO + o + 16);
                    #pragma unroll
                    for (int mi = 0; mi < 2; ++mi) {
                        mma16816(acc[mi][nt], Ah[mi], bh);
                        mma16816(acc[mi][nt], Al[mi], bh);
                        mma16816(acc[mi][nt], Ah[mi], bl);
                    }
                }
            }
            ++q;
        }

        // ---- epilogue ----
        if (MODE == 0) {
            #pragma unroll
            for (int mi = 0; mi < 2; ++mi) {
                const int co_a = co_base + mi * 16 + (lane >> 2);
                float sa = 0.f, qa = 0.f, sbx = 0.f, qb = 0.f;
                #pragma unroll
                for (int nt = 0; nt < 4; ++nt) {
                    int gp = nq * 32 + nt * 8 + (lane & 3) * 2;
                    float d0 = acc[mi][nt][0], d1 = acc[mi][nt][1];
                    float d2 = acc[mi][nt][2], d3 = acc[mi][nt][3];
                    *(float2*)&out[((size_t)(b * CH + co_a) << 12) + h0 * HW + gp]     = make_float2(d0, d1);
                    *(float2*)&out[((size_t)(b * CH + co_a + 8) << 12) + h0 * HW + gp] = make_float2(d2, d3);
                    sa += d0 + d1; qa += d0 * d0 + d1 * d1;
                    sbx += d2 + d3; qb += d2 * d2 + d3 * d3;
                }
                sa += __shfl_xor_sync(0xffffffffu, sa, 1); sa += __shfl_xor_sync(0xffffffffu, sa, 2);
                qa += __shfl_xor_sync(0xffffffffu, qa, 1); qa += __shfl_xor_sync(0xffffffffu, qa, 2);
                sbx += __shfl_xor_sync(0xffffffffu, sbx, 1); sbx += __shfl_xor_sync(0xffffffffu, sbx, 2);
                qb += __shfl_xor_sync(0xffffffffu, qb, 1); qb += __shfl_xor_sync(0xffffffffu, qb, 2);
                if ((lane & 3) == 0) {
                    atomicAdd(&stats[co_a], sa);      atomicAdd(&stats[CH + co_a], qa);
                    atomicAdd(&stats[co_a + 8], sbx); atomicAdd(&stats[CH + co_a + 8], qb);
                }
            }
        } else if (s == 2) {
            // g: direct [b][co][m] bf16 hi/lo
            #pragma unroll
            for (int mi = 0; mi < 2; ++mi) {
                const int co_a = co_base + mi * 16 + (lane >> 2);
                float bva = gbias[co_a], bvb = gbias[co_a + 8];
                #pragma unroll
                for (int nt = 0; nt < 4; ++nt) {
                    int gp = nq * 32 + nt * 8 + (lane & 3) * 2;
                    float d0 = acc[mi][nt][0] + bva, d1 = acc[mi][nt][1] + bva;
                    float d2 = acc[mi][nt][2] + bvb, d3 = acc[mi][nt][3] + bvb;
                    __nv_bfloat162 h01 = __floats2bfloat162_rn(d0, d1);
                    __nv_bfloat162 h23 = __floats2bfloat162_rn(d2, d3);
                    __nv_bfloat162 l01 = __floats2bfloat162_rn(d0 - __bfloat162float(h01.x),
                                                               d1 - __bfloat162float(h01.y));
                    __nv_bfloat162 l23 = __floats2bfloat162_rn(d2 - __bfloat162float(h23.x),
                                                               d3 - __bfloat162float(h23.y));
                    size_t oa = ((size_t)(b * CH + co_a) << 12) + h0 * HW + gp;
                    size_t ob = ((size_t)(b * CH + co_a + 8) << 12) + h0 * HW + gp;
                    *(__nv_bfloat162*)&gH[oa] = h01; *(__nv_bfloat162*)&gL[oa] = l01;
                    *(__nv_bfloat162*)&gH[ob] = h23; *(__nv_bfloat162*)&gL[ob] = l23;
                }
            }
        } else {
            // theta/phi: stage [px][co], emit transposed [b][n][c] hi/lo
            const float* bias = s ? phb : thb;
            float* so = (float*)(smem + SOUT);
            __syncthreads();
            #pragma unroll
            for (int mi = 0; mi < 2; ++mi) {
                const int co_a = co_base + mi * 16 + (lane >> 2);
                float bva = bias[co_a], bvb = bias[co_a + 8];
                #pragma unroll
                for (int nt = 0; nt < 4; ++nt) {
                    int gp = nq * 32 + nt * 8 + (lane & 3) * 2;
                    so[gp * 66 + co_a]           = acc[mi][nt][0] + bva;
                    so[(gp + 1) * 66 + co_a]     = acc[mi][nt][1] + bva;
                    so[gp * 66 + co_a + 8]       = acc[mi][nt][2] + bvb;
                    so[(gp + 1) * 66 + co_a + 8] = acc[mi][nt][3] + bvb;
                }
            }
            __syncthreads();
            {
                const int p = tid >> 1, cg = (tid & 1) * 32;
                const float* row = so + p * 66 + cg;
                __nv_bfloat16 hv[32], lv[32];
                #pragma unroll
                for (int k = 0; k < 32; ++k) {
                    float v = row[k];
                    hv[k] = __float2bfloat16_rn(v);
                    lv[k] = __float2bfloat16_rn(v - __bfloat162float(hv[k]));
                }
                __nv_bfloat16* H = s ? phH : thH;
                __nv_bfloat16* L = s ? phL : thL;
                size_t dst = ((size_t)b * NPIX + h0 * HW + p) * 64 + cg;
                *(uint4*)&H[dst]      = ((uint4*)hv)[0];
                *(uint4*)&H[dst + 8]  = ((uint4*)hv)[1];
                *(uint4*)&H[dst + 16] = ((uint4*)hv)[2];
                *(uint4*)&H[dst + 24] = ((uint4*)hv)[3];
                *(uint4*)&L[dst]      = ((uint4*)lv)[0];
                *(uint4*)&L[dst + 8]  = ((uint4*)lv)[1];
                *(uint4*)&L[dst + 16] = ((uint4*)lv)[2];
                *(uint4*)&L[dst + 24] = ((uint4*)lv)[3];
            }
        }
    }
}

__global__ void bnfinalize_kernel(const float* __restrict__ stats,
                                  float* __restrict__ mean, float* __restrict__ rstd)
{
    int c = threadIdx.x;
    const float invN = 1.f / (BATCH * NPIX);
    float m = stats[c] * invN;
    float v = stats[CH + c] * invN - m * m;
    mean[c] = m;
    rstd[c] = rsqrtf(v + EPSBN);
}

__global__ void __launch_bounds__(256) bnapply_kernel(
    const float* __restrict__ v, const float* __restrict__ mean,
    const float* __restrict__ rstd, const float* __restrict__ gamma,
    const float* __restrict__ beta, float* __restrict__ out)
{
    int i = blockIdx.x * 256 + threadIdx.x;
    int c = (i >> 12) & 63;
    float r = (v[i] - mean[c]) * rstd[c] * gamma[c] + beta[c];
    out[i] = fmaxf(r, 0.f);
}

// ---------------------------------------------------------------------------
// Fused attention + 1x1 W conv + residual -> z   (unchanged from R9)
// ---------------------------------------------------------------------------
#define FA_TH_HI 0
#define FA_TH_LO 16384
#define FA_BUF0  32768
#define FA_BUF1  98304
#define FA_PH    0
#define FA_PL    16384
#define FA_GH    32768
#define FA_GL    49152
#define FA_P     163840
#define FA_RS    196608
#define FA_SMEM  197120
#define EP_SY    0
#define EP_SW    36864
#define EP_SB    53504
#define EP_SZ    57344

__global__ void __launch_bounds__(256, 1) attn_fused_kernel(
    const __nv_bfloat16* __restrict__ thT_hi, const __nv_bfloat16* __restrict__ thT_lo,
    const __nv_bfloat16* __restrict__ phT_hi, const __nv_bfloat16* __restrict__ phT_lo,
    const __nv_bfloat16* __restrict__ g_hi,   const __nv_bfloat16* __restrict__ g_lo,
    const float* __restrict__ Ww, const float* __restrict__ Wb,
    const float* __restrict__ x, float* __restrict__ z)
{
    extern __shared__ __align__(128) char smem[];
    const uint32_t sb = smem_u32(smem);
    const int tid = threadIdx.x, w = tid >> 5, lane = tid & 31;
    const int n0 = blockIdx.x * 128, b = blockIdx.y;
    const int wn = w & 3, wm = w >> 2;

    float* sRS = (float*)(smem + FA_RS);
    if (tid < 128) sRS[tid] = 0.f;

    {
        const uint4* Ah = (const uint4*)(thT_hi + ((size_t)b * NPIX + n0) * 64);
        const uint4* Al = (const uint4*)(thT_lo + ((size_t)b * NPIX + n0) * 64);
        for (int i = tid; i < 1024; i += 256) {
            uint32_t off = SW128((uint32_t)(i >> 3) * 128 + (i & 7) * 16);
            *(uint4*)(smem + FA_TH_HI + off) = Ah[i];
            *(uint4*)(smem + FA_TH_LO + off) = Al[i];
        }
    }

    const char* phh = (const char*)(phT_hi + (size_t)b * NPIX * 64);
    const char* phl = (const char*)(phT_lo + (size_t)b * NPIX * 64);

    auto load_chunk = [&](int mb, uint32_t buf) {
        const char* ph = phh + (size_t)mb * 128;
        const char* pl = phl + (size_t)mb * 128;
        for (int i = tid; i < 1024; i += 256) {
            uint32_t off = SW128((uint32_t)(i >> 3) * 128 + (i & 7) * 16);
            cpasync16(sb + buf + FA_PH + off, ph + i * 16);
            cpasync16(sb + buf + FA_PL + off, pl + i * 16);
        }
        for (int i = tid; i < 1024; i += 256) {
            int row = i >> 4, seg = i & 15;
            uint32_t off = (uint32_t)(seg >> 3) * 8192 + SW128((uint32_t)row * 128 + (seg & 7) * 16);
            const size_t go = ((size_t)(b * CH + row)) * NPIX + mb + seg * 8;
            cpasync16(sb + buf + FA_GH + off, g_hi + go);
            cpasync16(sb + buf + FA_GL + off, g_lo + go);
        }
        cpasync_commit();
    };

    load_chunk(0, FA_BUF0);
    cpasync_wait0();
    __syncthreads();

    float acco[2][4][4];
    #pragma unroll
    for (int i = 0; i < 2; ++i)
        #pragma unroll
        for (int j = 0; j < 4; ++j)
            #pragma unroll
            for (int k = 0; k < 4; ++k) acco[i][j][k] = 0.f;
    float rs[2][2] = {{0.f, 0.f}, {0.f, 0.f}};

    const int arow = (lane & 15), acol = (lane >> 4);
    const int brow = ((lane >> 4) << 3) + (lane & 7), bcol = ((lane >> 3) & 1);

    for (int c = 0; c < 32; ++c) {
        const uint32_t buf  = (c & 1) ? FA_BUF1 : FA_BUF0;
        const uint32_t nbuf = (c & 1) ? FA_BUF0 : FA_BUF1;
        if (c < 31) load_chunk((c + 1) * 128, nbuf);

        float accs[2][8][4];
        #pragma unroll
        for (int i = 0; i < 2; ++i)
            #pragma unroll
            for (int j = 0; j < 8; ++j)
                #pragma unroll
                for (int k = 0; k < 4; ++k) accs[i][j][k] = 0.f;

        #pragma unroll
        for (int k = 0; k < 4; ++k) {
            uint32_t aH[2][4], aL[2][4], bH[4][4], bL[4][4];
            #pragma unroll
            for (int fi = 0; fi < 2; ++fi) {
                uint32_t off = SW128((uint32_t)(wn * 32 + fi * 16 + arow) * 128 + (k * 2 + acol) * 16);
                ldsm4(aH[fi], sb + FA_TH_HI + off);
                ldsm4(aL[fi], sb + FA_TH_LO + off);
            }
            #pragma unroll
            for (int qd = 0; qd < 4; ++qd) {
                uint32_t off = SW128((uint32_t)(wm * 64 + qd * 16 + brow) * 128 + (k * 2 + bcol) * 16);
                ldsm4(bH[qd], sb + buf + FA_PH + off);
                ldsm4(bL[qd], sb + buf + FA_PL + off);
            }
            #pragma unroll
            for (int fi = 0; fi < 2; ++fi)
                #pragma unroll
                for (int qd = 0; qd < 4; ++qd) {
                    mma16816(accs[fi][2 * qd],     aH[fi], &bH[qd][0]);
                    mma16816(accs[fi][2 * qd + 1], aH[fi], &bH[qd][2]);
                    mma16816(accs[fi][2 * qd],     aH[fi], &bL[qd][0]);
                    mma16816(accs[fi][2 * qd + 1], aH[fi], &bL[qd][2]);
                    mma16816(accs[fi][2 * qd],     aL[fi], &bH[qd][0]);
                    mma16816(accs[fi][2 * qd + 1], aL[fi], &bH[qd][2]);
                }
        }

        #pragma unroll
        for (int fi = 0; fi < 2; ++fi) {
            const int n1 = wn * 32 + fi * 16 + (lane >> 2);
            #pragma unroll
            for (int bj = 0; bj < 8; ++bj) {
                const int ml = wm * 64 + bj * 8 + (lane & 3) * 2;
                const uint32_t pan = (uint32_t)(ml >> 6) * 16384;
                const int col = ml & 63;
                float e0 = __expf(accs[fi][bj][0]);
                float e1 = __expf(accs[fi][bj][1]);
                float e2 = __expf(accs[fi][bj][2]);
                float e3 = __expf(accs[fi][bj][3]);
                rs[fi][0] += e0 + e1; rs[fi][1] += e2 + e3;
                __nv_bfloat162 p01 = __floats2bfloat162_rn(e0, e1);
                __nv_bfloat162 p23 = __floats2bfloat162_rn(e2, e3);
                *(uint32_t*)(smem + FA_P + pan + SW128((uint32_t)n1 * 128 + col * 2))       = *(uint32_t*)&p01;
                *(uint32_t*)(smem + FA_P + pan + SW128((uint32_t)(n1 + 8) * 128 + col * 2)) = *(uint32_t*)&p23;
            }
        }
        __syncthreads();

        #pragma unroll
        for (int kk = 0; kk < 8; ++kk) {
            const uint32_t panA = (uint32_t)(kk >> 2) * 16384;
            const uint32_t panB = (uint32_t)(kk >> 2) * 8192;
            const int kc = kk & 3;
            uint32_t aP[2][4], bH[2][4], bL[2][4];
            #pragma unroll
            for (int fi = 0; fi < 2; ++fi) {
                uint32_t off = SW128((uint32_t)(wn * 32 + fi * 16 + arow) * 128 + (kc * 2 + acol) * 16);
                ldsm4(aP[fi], sb + FA_P + panA + off);
            }
            #pragma unroll
            for (int qd = 0; qd < 2; ++qd) {
                uint32_t off = SW128((uint32_t)(wm * 32 + qd * 16 + brow) * 128 + (kc * 2 + bcol) * 16);
                ldsm4(bH[qd], sb + buf + FA_GH + panB + off);
                ldsm4(bL[qd], sb + buf + FA_GL + panB + off);
            }
            #pragma unroll
            for (int fi = 0; fi < 2; ++fi)
                #pragma unroll
                for (int qd = 0; qd < 2; ++qd) {
                    mma16816(acco[fi][2 * qd],     aP[fi], &bH[qd][0]);
                    mma16816(acco[fi][2 * qd + 1], aP[fi], &bH[qd][2]);
                    mma16816(acco[fi][2 * qd],     aP[fi], &bL[qd][0]);
                    mma16816(acco[fi][2 * qd + 1], aP[fi], &bL[qd][2]);
                }
        }

        cpasync_wait0();
        __syncthreads();
    }

    #pragma unroll
    for (int fi = 0; fi < 2; ++fi) {
        const int n1 = wn * 32 + fi * 16 + (lane >> 2);
        float s1 = rs[fi][0], s2 = rs[fi][1];
        s1 += __shfl_xor_sync(0xffffffffu, s1, 1);
        s1 += __shfl_xor_sync(0xffffffffu, s1, 2);
        s2 += __shfl_xor_sync(0xffffffffu, s2, 1);
        s2 += __shfl_xor_sync(0xffffffffu, s2, 2);
        if ((lane & 3) == 0) {
            atomicAdd(&sRS[n1], s1);
            atomicAdd(&sRS[n1 + 8], s2);
        }
    }
    __syncthreads();

    float inv[2][2];
    #pragma unroll
    for (int fi = 0; fi < 2; ++fi) {
        int n1 = wn * 32 + fi * 16 + (lane >> 2);
        inv[fi][0] = 1.f / sRS[n1];
        inv[fi][1] = 1.f / sRS[n1 + 8];
    }
    float* sY = (float*)(smem + EP_SY);
    #pragma unroll
    for (int fi = 0; fi < 2; ++fi) {
        int n1 = wn * 32 + fi * 16 + (lane >> 2);
        #pragma unroll
        for (int bj = 0; bj < 4; ++bj) {
            int cl = wm * 32 + bj * 8 + (lane & 3) * 2;
            sY[n1 * 65 + cl]           = acco[fi][bj][0] * inv[fi][0];
            sY[n1 * 65 + cl + 1]       = acco[fi][bj][1] * inv[fi][0];
            sY[(n1 + 8) * 65 + cl]     = acco[fi][bj][2] * inv[fi][1];
            sY[(n1 + 8) * 65 + cl + 1] = acco[fi][bj][3] * inv[fi][1];
        }
    }
    float* sWm = (float*)(smem + EP_SW);
    float* sBv = (float*)(smem + EP_SB);
    for (int i = tid; i < 4096; i += 256) sWm[(i >> 6) * 65 + (i & 63)] = Ww[i];
    if (tid < 64) sBv[tid] = Wb[tid];
    __syncthreads();

    float* sZ = (float*)(smem + EP_SZ);
    {
        const int nb = (tid >> 3) * 4;
        const int cb = (tid & 7) * 8;
        ull a2[8][2];
        #pragma unroll
        for (int j = 0; j < 8; ++j) { a2[j][0] = 0ull; a2[j][1] = 0ull; }
        #pragma unroll 8
        for (int ci = 0; ci < 64; ++ci) {
            ull y01 = pk2(sY[nb * 65 + ci],       sY[(nb + 1) * 65 + ci]);
            ull y23 = pk2(sY[(nb + 2) * 65 + ci], sY[(nb + 3) * 65 + ci]);
            #pragma unroll
            for (int j = 0; j < 8; ++j) {
                float wv = sWm[(cb + j) * 65 + ci];
                ull wd = pk2(wv, wv);
                fma2(a2[j][0], wd, y01);
                fma2(a2[j][1], wd, y23);
            }
        }
        #pragma unroll
        for (int j = 0; j < 8; ++j) {
            float bv = sBv[cb + j];
            float2 v01 = upk2(a2[j][0]);
            float2 v23 = upk2(a2[j][1]);
            sZ[nb * 65 + cb + j]       = v01.x + bv;
            sZ[(nb + 1) * 65 + cb + j] = v01.y + bv;
            sZ[(nb + 2) * 65 + cb + j] = v23.x + bv;
            sZ[(nb + 3) * 65 + cb + j] = v23.y + bv;
        }
    }
    __syncthreads();

    for (int i = tid; i < 8192; i += 256) {
        int c = i >> 7, n = i & 127;
        size_t o = ((size_t)(b * CH + c) << 12) + n0 + n;
        z[o] = sZ[n * 65 + c] + x[o];
    }
}

// ---------------------------------------------------------------------------
// Launch
// ---------------------------------------------------------------------------
extern "C" void kernel_launch(void* const* d_in, const int* in_sizes, int n_in,
                              void* d_out, int out_size)
{
    const float* x       = (const float*)d_in[0];
    const float* conv1_w = (const float*)d_in[1];
    const float* bn1_g   = (const float*)d_in[2];
    const float* bn1_b   = (const float*)d_in[3];
    const float* theta_w = (const float*)d_in[4];
    const float* theta_b = (const float*)d_in[5];
    const float* phi_w   = (const float*)d_in[6];
    const float* phi_b   = (const float*)d_in[7];
    const float* gw      = (const float*)d_in[8];
    const float* gb      = (const float*)d_in[9];
    const float* W_w     = (const float*)d_in[10];
    const float* W_b     = (const float*)d_in[11];
    const float* conv2_w = (const float*)d_in[12];
    const float* bn2_g   = (const float*)d_in[13];
    const float* bn2_b   = (const float*)d_in[14];
    float* out = (float*)d_out;

    float *p_c1, *p_z, *p_mean, *p_rstd, *p_stats;
    __nv_bfloat16 *p_wm, *p_thH, *p_thL, *p_phH, *p_phL, *p_gH, *p_gL;
    cudaGetSymbolAddress((void**)&p_c1,   g_c1raw);
    cudaGetSymbolAddress((void**)&p_z,    g_z);
    cudaGetSymbolAddress((void**)&p_mean, g_mean);
    cudaGetSymbolAddress((void**)&p_rstd, g_rstd);
    cudaGetSymbolAddress((void**)&p_stats, g_stats);
    cudaGetSymbolAddress((void**)&p_wm,   g_wmma);
    cudaGetSymbolAddress((void**)&p_thH,  g_thT_hi);
    cudaGetSymbolAddress((void**)&p_thL,  g_thT_lo);
    cudaGetSymbolAddress((void**)&p_phH,  g_phT_hi);
    cudaGetSymbolAddress((void**)&p_phL,  g_phT_lo);
    cudaGetSymbolAddress((void**)&p_gH,   g_g_hi);
    cudaGetSymbolAddress((void**)&p_gL,   g_g_lo);

    cudaFuncSetAttribute(conv_mma_kernel<0>, cudaFuncAttributeMaxDynamicSharedMemorySize, CV_SMEM0);
    cudaFuncSetAttribute(conv_mma_kernel<1>, cudaFuncAttributeMaxDynamicSharedMemorySize, CV_SMEM1);
    cudaFuncSetAttribute(attn_fused_kernel,  cudaFuncAttributeMaxDynamicSharedMemorySize, FA_SMEM);

    wtrans_mma_kernel<<<720, 256>>>(conv1_w, theta_w, phi_w, gw, conv2_w, p_wm);

    // conv1 (+BN1 stats)
    cudaMemsetAsync(p_stats, 0, 2 * CH * sizeof(float));
    conv_mma_kernel<0><<<dim3(32, BATCH), 256, CV_SMEM0>>>(
        x, p_wm, p_c1, p_stats,
        nullptr, nullptr, nullptr, nullptr, nullptr, nullptr, nullptr,
        nullptr, nullptr, nullptr, nullptr, nullptr, nullptr);
    bnfinalize_kernel<<<1, 64>>>(p_stats, p_mean, p_rstd);

    // fused projections (BN1 on input; direct bf16 hi/lo outputs)
    conv_mma_kernel<1><<<dim3(32, BATCH), 256, CV_SMEM1>>>(
        p_c1, p_wm + (size_t)9 * 2 * 4096, nullptr, nullptr,
        p_mean, p_rstd, bn1_g, bn1_b, theta_b, phi_b, gb,
        p_thH, p_thL, p_phH, p_phL, p_gH, p_gL);

    // fused attention + 1x1 W conv + residual -> z
    attn_fused_kernel<<<dim3(32, BATCH), 256, FA_SMEM>>>(
        p_thH, p_thL, p_phH, p_phL, p_gH, p_gL, W_w, W_b, x, p_z);

    // conv2 (+BN2 stats) + final BN apply
    cudaMemsetAsync(p_stats, 0, 2 * CH * sizeof(float));
    conv_mma_kernel<0><<<dim3(32, BATCH), 256, CV_SMEM0>>>(
        p_z, p_wm + (size_t)4 * 9 * 2 * 4096, p_c1, p_stats,
        nullptr, nullptr, nullptr, nullptr, nullptr, nullptr, nullptr,
        nullptr, nullptr, nullptr, nullptr, nullptr, nullptr);
    bnfinalize_kernel<<<1, 64>>>(p_stats, p_mean, p_rstd);
    bnapply_kernel<<<(BATCH * CH * NPIX) / 256, 256>>>(p_c1, p_mean, p_rstd, bn2_g, bn2_b, out);
}

// round 12
// speedup vs baseline: 5.2661x; 1.0085x over previous
#include <cuda_runtime.h>
#include <cuda_bf16.h>
#include <cstdint>

typedef unsigned long long ull;

#define BATCH 4
#define CH    64
#define HW    64
#define NPIX  4096
#define EPSBN 1e-5f
#define LOG2E_F 1.4426950408889634f

// ---------------------------------------------------------------------------
// Scratch
// ---------------------------------------------------------------------------
__device__ float g_c1raw[BATCH * CH * NPIX];
__device__ float g_z    [BATCH * CH * NPIX];
__device__ float g_mean[CH];
__device__ float g_rstd[CH];
__device__ float g_stats[2 * CH];
__device__ __nv_bfloat16 g_wmma[5 * 9 * 2 * CH * CH];   // [set][tap][hi/lo][co][ci]

// bf16 operands for mma.sync
__device__ __nv_bfloat16 g_thT_hi[BATCH * NPIX * CH];   // [b][n][c] (pre-scaled by log2e)
__device__ __nv_bfloat16 g_thT_lo[BATCH * NPIX * CH];
__device__ __nv_bfloat16 g_phT_hi[BATCH * NPIX * CH];   // [b][m][c]
__device__ __nv_bfloat16 g_phT_lo[BATCH * NPIX * CH];
__device__ __nv_bfloat16 g_g_hi [BATCH * CH * NPIX];    // [b][c][m]
__device__ __nv_bfloat16 g_g_lo [BATCH * CH * NPIX];

// ---------------------------------------------------------------------------
// f32x2 helpers
// ---------------------------------------------------------------------------
__device__ __forceinline__ ull pk2(float lo, float hi) {
    ull r; asm("mov.b64 %0, {%1, %2};" : "=l"(r) : "f"(lo), "f"(hi)); return r;
}
__device__ __forceinline__ void fma2(ull& d, ull a, ull b) {
    asm("fma.rn.f32x2 %0, %1, %2, %0;" : "+l"(d) : "l"(a), "l"(b));
}
__device__ __forceinline__ float2 upk2(ull v) {
    float2 r; asm("mov.b64 {%0, %1}, %2;" : "=f"(r.x), "=f"(r.y) : "l"(v)); return r;
}
__device__ __forceinline__ float ex2f(float x) {
    float r; asm("ex2.approx.f32 %0, %1;" : "=f"(r) : "f"(x)); return r;
}

// ---------------------------------------------------------------------------
// mma.sync / cp.async helpers
// ---------------------------------------------------------------------------
__device__ __forceinline__ uint32_t smem_u32(const void* p) {
    uint32_t a;
    asm("{ .reg .u64 t; cvta.to.shared.u64 t, %1; cvt.u32.u64 %0, t; }" : "=r"(a) : "l"(p));
    return a;
}
#define SW128(o) ((o) ^ ((((uint32_t)(o)) >> 3) & 0x70))

__device__ __forceinline__ void ldsm4(uint32_t* r, uint32_t addr) {
    asm volatile("ldmatrix.sync.aligned.m8n8.x4.shared.b16 {%0,%1,%2,%3}, [%4];"
        : "=r"(r[0]), "=r"(r[1]), "=r"(r[2]), "=r"(r[3]) : "r"(addr));
}
__device__ __forceinline__ void mma16816(float* d, const uint32_t* a, const uint32_t* b) {
    asm volatile("mma.sync.aligned.m16n8k16.row.col.f32.bf16.bf16.f32 "
        "{%0,%1,%2,%3},{%4,%5,%6,%7},{%8,%9},{%0,%1,%2,%3};"
        : "+f"(d[0]), "+f"(d[1]), "+f"(d[2]), "+f"(d[3])
        : "r"(a[0]), "r"(a[1]), "r"(a[2]), "r"(a[3]), "r"(b[0]), "r"(b[1]));
}
__device__ __forceinline__ void cpasync16(uint32_t dst, const void* src) {
    asm volatile("cp.async.cg.shared.global [%0], [%1], 16;" :: "r"(dst), "l"(src));
}
__device__ __forceinline__ void cpasync_commit() {
    asm volatile("cp.async.commit_group;" ::: "memory");
}
__device__ __forceinline__ void cpasync_wait0() {
    asm volatile("cp.async.wait_group 0;" ::: "memory");
}

// ---------------------------------------------------------------------------
// Weight prep: w[co][ci][kh][kw] fp32 -> [set][tap][hi/lo][co][ci] bf16
// ---------------------------------------------------------------------------
__global__ void wtrans_mma_kernel(
    const float* __restrict__ w0, const float* __restrict__ w1,
    const float* __restrict__ w2, const float* __restrict__ w3,
    const float* __restrict__ w4, __nv_bfloat16* __restrict__ wm)
{
    const float* ws[5] = {w0, w1, w2, w3, w4};
    int i = blockIdx.x * 256 + threadIdx.x;
    if (i < 5 * 9 * 4096) {
        int set = i / 36864, rem = i % 36864;
        int tap = rem / 4096, rem2 = rem % 4096;
        int co = rem2 >> 6, ci = rem2 & 63;
        int kh = tap / 3, kw = tap % 3;
        float v = ws[set][co * 576 + ci * 9 + kh * 3 + kw];
        __nv_bfloat16 h = __float2bfloat16_rn(v);
        __nv_bfloat16 l = __float2bfloat16_rn(v - __bfloat162float(h));
        size_t base = ((size_t)(set * 9 + tap) * 2) * 4096 + co * 64 + ci;
        wm[base] = h;
        wm[base + 4096] = l;
    }
}

// ---------------------------------------------------------------------------
// HMMA implicit-GEMM 3x3 conv, co-split (each CTA = 32 co x 128 px).
// MODE 0: 1 weight set, fp32 out + fused BN stats (atomics).
// MODE 1: 3 sets (theta,phi,g) over BN+ReLU'd input; bf16 hi/lo outputs;
//         theta pre-scaled by log2e.
// grid (32 h-pairs, B, 2 co-halves), 256 threads, 2 CTAs/SM.
// ---------------------------------------------------------------------------
#define SXT_HI 0
#define SXT_LO 38016
#define SWB0   76032
#define SWB1   85248
#define SOUT   94464
#define SBN    111872
#define CV_SMEM0 94464
#define CV_SMEM1 112384

template<int MODE>
__global__ void __launch_bounds__(256, 2) conv_mma_kernel(
    const float* __restrict__ in, const __nv_bfloat16* __restrict__ wm,
    float* __restrict__ out, float* __restrict__ stats,
    const float* __restrict__ mean, const float* __restrict__ rstd,
    const float* __restrict__ gamma, const float* __restrict__ beta,
    const float* __restrict__ thb, const float* __restrict__ phb,
    const float* __restrict__ gbias,
    __nv_bfloat16* __restrict__ thH, __nv_bfloat16* __restrict__ thL,
    __nv_bfloat16* __restrict__ phH, __nv_bfloat16* __restrict__ phL,
    __nv_bfloat16* __restrict__ gH,  __nv_bfloat16* __restrict__ gL)
{
    extern __shared__ __align__(128) char smem[];
    const uint32_t sb = smem_u32(smem);
    const int tid = threadIdx.x, w = tid >> 5, lane = tid & 31;
    const int h0 = blockIdx.x * 2;
    const int b  = blockIdx.y;
    const int co_off = blockIdx.z * 32;
    const int mpair = w & 1, nq = w >> 1;
    const int co_base = mpair * 16;      // within this CTA's 32-co slab

    if (MODE == 1) {
        if (tid < 64) {
            float sc = rstd[tid] * gamma[tid];
            ((float*)(smem + SBN))[tid]      = sc;
            ((float*)(smem + SBN))[64 + tid] = beta[tid] - mean[tid] * sc;
        }
        __syncthreads();
    }

    // ---- stage transposed hi/lo input rows h0-1 .. h0+2 ----
    {
        const float* scl = (const float*)(smem + SBN);
        const float* shf = scl + 64;
        for (int i = tid; i < 512; i += 256) {
            int r = i >> 7, ci = (i >> 1) & 63, e = i & 1;
            uint32_t off = (uint32_t)((r * 66 + (e ? 65 : 0)) * 72 + ci) * 2;
            *(__nv_bfloat16*)(smem + SXT_HI + off) = __float2bfloat16_rn(0.f);
            *(__nv_bfloat16*)(smem + SXT_LO + off) = __float2bfloat16_rn(0.f);
        }
        #pragma unroll
        for (int j = 0; j < 16; ++j) {
            int e4 = tid + 256 * j;
            int w4 = (e4 & 15) * 4;
            int ci = (e4 >> 4) & 63;
            int ri = e4 >> 10;
            int row = h0 - 1 + ri;
            float4 v = make_float4(0.f, 0.f, 0.f, 0.f);
            if (row >= 0 && row < HW) {
                v = *(const float4*)&in[((size_t)(b * CH + ci) << 12) + row * HW + w4];
                if (MODE == 1) {
                    float s = scl[ci], t = shf[ci];
                    v.x = fmaxf(fmaf(v.x, s, t), 0.f);
                    v.y = fmaxf(fmaf(v.y, s, t), 0.f);
                    v.z = fmaxf(fmaf(v.z, s, t), 0.f);
                    v.w = fmaxf(fmaf(v.w, s, t), 0.f);
                }
            }
            const float vv[4] = {v.x, v.y, v.z, v.w};
            #pragma unroll
            for (int jj = 0; jj < 4; ++jj) {
                uint32_t off = (uint32_t)((ri * 66 + w4 + jj + 1) * 72 + ci) * 2;
                __nv_bfloat16 h = __float2bfloat16_rn(vv[jj]);
                *(__nv_bfloat16*)(smem + SXT_HI + off) = h;
                *(__nv_bfloat16*)(smem + SXT_LO + off) =
                    __float2bfloat16_rn(vv[jj] - __bfloat162float(h));
            }
        }
    }

    // weight tap load: 32 co x 64 ci x hi/lo, one 32B unit per thread
    const int wside = tid >> 7, wco = (tid >> 2) & 31, wqtr = tid & 3;
    auto load_w = [&](int q, int buf) {
        const __nv_bfloat16* s = wm + (size_t)q * 8192 + wside * 4096
                               + (co_off + wco) * 64 + wqtr * 16;
        uint32_t d = sb + (buf ? SWB1 : SWB0) + wside * 4608
                   + (uint32_t)(wco * 72 + wqtr * 16) * 2;
        cpasync16(d, s);
        cpasync16(d + 16, s + 8);
        cpasync_commit();
    };

    // lane decodes
    const int bci  = (lane & 3) * 4;
    const int bwn  = lane >> 2;
    const int arow = ((lane & 8) ? 8 : 0) + (lane & 7);
    const int acolh = (lane & 16) ? 8 : 0;

    const int NSETS = (MODE == 1) ? 3 : 1;
    const int NT = NSETS * 9;
    load_w(0, 0);
    int q = 0;

    for (int s = 0; s < NSETS; ++s) {
        float acc[4][4];
        #pragma unroll
        for (int nt = 0; nt < 4; ++nt)
            #pragma unroll
            for (int k = 0; k < 4; ++k) acc[nt][k] = 0.f;

        for (int tap = 0; tap < 9; ++tap) {
            cpasync_wait0();
            __syncthreads();
            if (q + 1 < NT) load_w(q + 1, (q + 1) & 1);

            const int dh = tap / 3, dw = tap % 3;
            const uint32_t swb = sb + ((q & 1) ? SWB1 : SWB0);
            int bb[4];
            #pragma unroll
            for (int nt = 0; nt < 4; ++nt) {
                int p0 = nq * 32 + nt * 8;
                int r = (p0 >> 6) + dh;
                int wc = (p0 & 63) + bwn + dw;
                bb[nt] = (r * 66 + wc) * 144 + bci;
            }
            #pragma unroll
            for (int k = 0; k < 4; ++k) {
                uint32_t Ah[4], Al[4];
                uint32_t ao = (uint32_t)((co_base + arow) * 72 + k * 16 + acolh) * 2;
                ldsm4(Ah, swb + ao);
                ldsm4(Al, swb + 4608 + ao);
                #pragma unroll
                for (int nt = 0; nt < 4; ++nt) {
                    int o = bb[nt] + k * 32;
                    uint32_t bh[2], bl[2];
                    bh[0] = *(const uint32_t*)(smem + SXT_HI + o);
                    bh[1] = *(const uint32_t*)(smem + SXT_HI + o + 16);
                    bl[0] = *(const uint32_t*)(smem + SXT_LO + o);
                    bl[1] = *(const uint32_t*)(smem + SXT_LO + o + 16);
                    mma16816(acc[nt], Ah, bh);
                    mma16816(acc[nt], Al, bh);
                    mma16816(acc[nt], Ah, bl);
                }
            }
            ++q;
        }

        // ---- epilogue ----
        if (MODE == 0) {
            const int co_a = co_off + co_base + (lane >> 2);
            float sa = 0.f, qa = 0.f, sbx = 0.f, qb = 0.f;
            #pragma unroll
            for (int nt = 0; nt < 4; ++nt) {
                int gp = nq * 32 + nt * 8 + (lane & 3) * 2;
                float d0 = acc[nt][0], d1 = acc[nt][1];
                float d2 = acc[nt][2], d3 = acc[nt][3];
                *(float2*)&out[((size_t)(b * CH + co_a) << 12) + h0 * HW + gp]     = make_float2(d0, d1);
                *(float2*)&out[((size_t)(b * CH + co_a + 8) << 12) + h0 * HW + gp] = make_float2(d2, d3);
                sa += d0 + d1; qa += d0 * d0 + d1 * d1;
                sbx += d2 + d3; qb += d2 * d2 + d3 * d3;
            }
            sa += __shfl_xor_sync(0xffffffffu, sa, 1); sa += __shfl_xor_sync(0xffffffffu, sa, 2);
            qa += __shfl_xor_sync(0xffffffffu, qa, 1); qa += __shfl_xor_sync(0xffffffffu, qa, 2);
            sbx += __shfl_xor_sync(0xffffffffu, sbx, 1); sbx += __shfl_xor_sync(0xffffffffu, sbx, 2);
            qb += __shfl_xor_sync(0xffffffffu, qb, 1); qb += __shfl_xor_sync(0xffffffffu, qb, 2);
            if ((lane & 3) == 0) {
                atomicAdd(&stats[co_a], sa);      atomicAdd(&stats[CH + co_a], qa);
                atomicAdd(&stats[co_a + 8], sbx); atomicAdd(&stats[CH + co_a + 8], qb);
            }
        } else if (s == 2) {
            // g: direct [b][co][m] bf16 hi/lo
            const int co_a = co_off + co_base + (lane >> 2);
            float bva = gbias[co_a], bvb = gbias[co_a + 8];
            #pragma unroll
            for (int nt = 0; nt < 4; ++nt) {
                int gp = nq * 32 + nt * 8 + (lane & 3) * 2;
                float d0 = acc[nt][0] + bva, d1 = acc[nt][1] + bva;
                float d2 = acc[nt][2] + bvb, d3 = acc[nt][3] + bvb;
                __nv_bfloat162 h01 = __floats2bfloat162_rn(d0, d1);
                __nv_bfloat162 h23 = __floats2bfloat162_rn(d2, d3);
                __nv_bfloat162 l01 = __floats2bfloat162_rn(d0 - __bfloat162float(h01.x),
                                                           d1 - __bfloat162float(h01.y));
                __nv_bfloat162 l23 = __floats2bfloat162_rn(d2 - __bfloat162float(h23.x),
                                                           d3 - __bfloat162float(h23.y));
                size_t oa = ((size_t)(b * CH + co_a) << 12) + h0 * HW + gp;
                size_t ob = ((size_t)(b * CH + co_a + 8) << 12) + h0 * HW + gp;
                *(__nv_bfloat162*)&gH[oa] = h01; *(__nv_bfloat162*)&gL[oa] = l01;
                *(__nv_bfloat162*)&gH[ob] = h23; *(__nv_bfloat162*)&gL[ob] = l23;
            }
        } else {
            // theta/phi: stage [px][co32], emit transposed [b][n][c] hi/lo
            // theta additionally pre-scaled by log2e (softmax via ex2).
            const float* bias = s ? phb : thb;
            const float osc = s ? 1.f : LOG2E_F;
            float* so = (float*)(smem + SOUT);     // 128 x 34
            __syncthreads();
            {
                const int co_l = co_base + (lane >> 2);
                float bva = bias[co_off + co_l], bvb = bias[co_off + co_l + 8];
                #pragma unroll
                for (int nt = 0; nt < 4; ++nt) {
                    int gp = nq * 32 + nt * 8 + (lane & 3) * 2;
                    so[gp * 34 + co_l]           = (acc[nt][0] + bva) * osc;
                    so[(gp + 1) * 34 + co_l]     = (acc[nt][1] + bva) * osc;
                    so[gp * 34 + co_l + 8]       = (acc[nt][2] + bvb) * osc;
                    so[(gp + 1) * 34 + co_l + 8] = (acc[nt][3] + bvb) * osc;
                }
            }
            __syncthreads();
            {
                const int p = tid >> 1, half = tid & 1;
                const float* row = so + p * 34 + half * 16;
                __nv_bfloat16 hv[16], lv[16];
                #pragma unroll
                for (int k = 0; k < 16; ++k) {
                    float v = row[k];
                    hv[k] = __float2bfloat16_rn(v);
                    lv[k] = __float2bfloat16_rn(v - __bfloat162float(hv[k]));
                }
                __nv_bfloat16* H = s ? phH : thH;
                __nv_bfloat16* L = s ? phL : thL;
                size_t dst = ((size_t)b * NPIX + h0 * HW + p) * 64 + co_off + half * 16;
                *(uint4*)&H[dst]     = ((uint4*)hv)[0];
                *(uint4*)&H[dst + 8] = ((uint4*)hv)[1];
                *(uint4*)&L[dst]     = ((uint4*)lv)[0];
                *(uint4*)&L[dst + 8] = ((uint4*)lv)[1];
            }
        }
    }
}

__global__ void bnfinalize_kernel(const float* __restrict__ stats,
                                  float* __restrict__ mean, float* __restrict__ rstd)
{
    int c = threadIdx.x;
    const float invN = 1.f / (BATCH * NPIX);
    float m = stats[c] * invN;
    float v = stats[CH + c] * invN - m * m;
    mean[c] = m;
    rstd[c] = rsqrtf(v + EPSBN);
}

__global__ void __launch_bounds__(256) bnapply_kernel(
    const float* __restrict__ v, const float* __restrict__ mean,
    const float* __restrict__ rstd, const float* __restrict__ gamma,
    const float* __restrict__ beta, float* __restrict__ out)
{
    int i = blockIdx.x * 256 + threadIdx.x;
    int c = (i >> 12) & 63;
    float r = (v[i] - mean[c]) * rstd[c] * gamma[c] + beta[c];
    out[i] = fmaxf(r, 0.f);
}

// ---------------------------------------------------------------------------
// Fused attention + 1x1 W conv + residual -> z
// (theta pre-scaled by log2e, softmax via ex2)
// ---------------------------------------------------------------------------
#define FA_TH_HI 0
#define FA_TH_LO 16384
#define FA_BUF0  32768
#define FA_BUF1  98304
#define FA_PH    0
#define FA_PL    16384
#define FA_GH    32768
#define FA_GL    49152
#define FA_P     163840
#define FA_RS    196608
#define FA_SMEM  197120
#define EP_SY    0
#define EP_SW    36864
#define EP_SB    53504
#define EP_SZ    57344

__global__ void __launch_bounds__(256, 1) attn_fused_kernel(
    const __nv_bfloat16* __restrict__ thT_hi, const __nv_bfloat16* __restrict__ thT_lo,
    const __nv_bfloat16* __restrict__ phT_hi, const __nv_bfloat16* __restrict__ phT_lo,
    const __nv_bfloat16* __restrict__ g_hi,   const __nv_bfloat16* __restrict__ g_lo,
    const float* __restrict__ Ww, const float* __restrict__ Wb,
    const float* __restrict__ x, float* __restrict__ z)
{
    extern __shared__ __align__(128) char smem[];
    const uint32_t sb = smem_u32(smem);
    const int tid = threadIdx.x, w = tid >> 5, lane = tid & 31;
    const int n0 = blockIdx.x * 128, b = blockIdx.y;
    const int wn = w & 3, wm = w >> 2;

    float* sRS = (float*)(smem + FA_RS);
    if (tid < 128) sRS[tid] = 0.f;

    {
        const uint4* Ah = (const uint4*)(thT_hi + ((size_t)b * NPIX + n0) * 64);
        const uint4* Al = (const uint4*)(thT_lo + ((size_t)b * NPIX + n0) * 64);
        for (int i = tid; i < 1024; i += 256) {
            uint32_t off = SW128((uint32_t)(i >> 3) * 128 + (i & 7) * 16);
            *(uint4*)(smem + FA_TH_HI + off) = Ah[i];
            *(uint4*)(smem + FA_TH_LO + off) = Al[i];
        }
    }

    const char* phh = (const char*)(phT_hi + (size_t)b * NPIX * 64);
    const char* phl = (const char*)(phT_lo + (size_t)b * NPIX * 64);

    auto load_chunk = [&](int mb, uint32_t buf) {
        const char* ph = phh + (size_t)mb * 128;
        const char* pl = phl + (size_t)mb * 128;
        for (int i = tid; i < 1024; i += 256) {
            uint32_t off = SW128((uint32_t)(i >> 3) * 128 + (i & 7) * 16);
            cpasync16(sb + buf + FA_PH + off, ph + i * 16);
            cpasync16(sb + buf + FA_PL + off, pl + i * 16);
        }
        for (int i = tid; i < 1024; i += 256) {
            int row = i >> 4, seg = i & 15;
            uint32_t off = (uint32_t)(seg >> 3) * 8192 + SW128((uint32_t)row * 128 + (seg & 7) * 16);
            const size_t go = ((size_t)(b * CH + row)) * NPIX + mb + seg * 8;
            cpasync16(sb + buf + FA_GH + off, g_hi + go);
            cpasync16(sb + buf + FA_GL + off, g_lo + go);
        }
        cpasync_commit();
    };

    load_chunk(0, FA_BUF0);
    cpasync_wait0();
    __syncthreads();

    float acco[2][4][4];
    #pragma unroll
    for (int i = 0; i < 2; ++i)
        #pragma unroll
        for (int j = 0; j < 4; ++j)
            #pragma unroll
            for (int k = 0; k < 4; ++k) acco[i][j][k] = 0.f;
    float rs[2][2] = {{0.f, 0.f}, {0.f, 0.f}};

    const int arow = (lane & 15), acol = (lane >> 4);
    const int brow = ((lane >> 4) << 3) + (lane & 7), bcol = ((lane >> 3) & 1);

    for (int c = 0; c < 32; ++c) {
        const uint32_t buf  = (c & 1) ? FA_BUF1 : FA_BUF0;
        const uint32_t nbuf = (c & 1) ? FA_BUF0 : FA_BUF1;
        if (c < 31) load_chunk((c + 1) * 128, nbuf);

        float accs[2][8][4];
        #pragma unroll
        for (int i = 0; i < 2; ++i)
            #pragma unroll
            for (int j = 0; j < 8; ++j)
                #pragma unroll
                for (int k = 0; k < 4; ++k) accs[i][j][k] = 0.f;

        #pragma unroll
        for (int k = 0; k < 4; ++k) {
            uint32_t aH[2][4], aL[2][4], bH[4][4], bL[4][4];
            #pragma unroll
            for (int fi = 0; fi < 2; ++fi) {
                uint32_t off = SW128((uint32_t)(wn * 32 + fi * 16 + arow) * 128 + (k * 2 + acol) * 16);
                ldsm4(aH[fi], sb + FA_TH_HI + off);
                ldsm4(aL[fi], sb + FA_TH_LO + off);
            }
            #pragma unroll
            for (int qd = 0; qd < 4; ++qd) {
                uint32_t off = SW128((uint32_t)(wm * 64 + qd * 16 + brow) * 128 + (k * 2 + bcol) * 16);
                ldsm4(bH[qd], sb + buf + FA_PH + off);
                ldsm4(bL[qd], sb + buf + FA_PL + off);
            }
            #pragma unroll
            for (int fi = 0; fi < 2; ++fi)
                #pragma unroll
                for (int qd = 0; qd < 4; ++qd) {
                    mma16816(accs[fi][2 * qd],     aH[fi], &bH[qd][0]);
                    mma16816(accs[fi][2 * qd + 1], aH[fi], &bH[qd][2]);
                    mma16816(accs[fi][2 * qd],     aH[fi], &bL[qd][0]);
                    mma16816(accs[fi][2 * qd + 1], aH[fi], &bL[qd][2]);
                    mma16816(accs[fi][2 * qd],     aL[fi], &bH[qd][0]);
                    mma16816(accs[fi][2 * qd + 1], aL[fi], &bH[qd][2]);
                }
        }

        #pragma unroll
        for (int fi = 0; fi < 2; ++fi) {
            const int n1 = wn * 32 + fi * 16 + (lane >> 2);
            #pragma unroll
            for (int bj = 0; bj < 8; ++bj) {
                const int ml = wm * 64 + bj * 8 + (lane & 3) * 2;
                const uint32_t pan = (uint32_t)(ml >> 6) * 16384;
                const int col = ml & 63;
                float e0 = ex2f(accs[fi][bj][0]);
                float e1 = ex2f(accs[fi][bj][1]);
                float e2 = ex2f(accs[fi][bj][2]);
                float e3 = ex2f(accs[fi][bj][3]);
                rs[fi][0] += e0 + e1; rs[fi][1] += e2 + e3;
                __nv_bfloat162 p01 = __floats2bfloat162_rn(e0, e1);
                __nv_bfloat162 p23 = __floats2bfloat162_rn(e2, e3);
                *(uint32_t*)(smem + FA_P + pan + SW128((uint32_t)n1 * 128 + col * 2))       = *(uint32_t*)&p01;
                *(uint32_t*)(smem + FA_P + pan + SW128((uint32_t)(n1 + 8) * 128 + col * 2)) = *(uint32_t*)&p23;
            }
        }
        __syncthreads();

        #pragma unroll
        for (int kk = 0; kk < 8; ++kk) {
            const uint32_t panA = (uint32_t)(kk >> 2) * 16384;
            const uint32_t panB = (uint32_t)(kk >> 2) * 8192;
            const int kc = kk & 3;
            uint32_t aP[2][4], bH[2][4], bL[2][4];
            #pragma unroll
            for (int fi = 0; fi < 2; ++fi) {
                uint32_t off = SW128((uint32_t)(wn * 32 + fi * 16 + arow) * 128 + (kc * 2 + acol) * 16);
                ldsm4(aP[fi], sb + FA_P + panA + off);
            }
            #pragma unroll
            for (int qd = 0; qd < 2; ++qd) {
                uint32_t off = SW128((uint32_t)(wm * 32 + qd * 16 + brow) * 128 + (kc * 2 + bcol) * 16);
                ldsm4(bH[qd], sb + buf + FA_GH + panB + off);
                ldsm4(bL[qd], sb + buf + FA_GL + panB + off);
            }
            #pragma unroll
            for (int fi = 0; fi < 2; ++fi)
                #pragma unroll
                for (int qd = 0; qd < 2; ++qd) {
                    mma16816(acco[fi][2 * qd],     aP[fi], &bH[qd][0]);
                    mma16816(acco[fi][2 * qd + 1], aP[fi], &bH[qd][2]);
                    mma16816(acco[fi][2 * qd],     aP[fi], &bL[qd][0]);
                    mma16816(acco[fi][2 * qd + 1], aP[fi], &bL[qd][2]);
                }
        }

        cpasync_wait0();
        __syncthreads();
    }

    #pragma unroll
    for (int fi = 0; fi < 2; ++fi) {
        const int n1 = wn * 32 + fi * 16 + (lane >> 2);
        float s1 = rs[fi][0], s2 = rs[fi][1];
        s1 += __shfl_xor_sync(0xffffffffu, s1, 1);
        s1 += __shfl_xor_sync(0xffffffffu, s1, 2);
        s2 += __shfl_xor_sync(0xffffffffu, s2, 1);
        s2 += __shfl_xor_sync(0xffffffffu, s2, 2);
        if ((lane & 3) == 0) {
            atomicAdd(&sRS[n1], s1);
            atomicAdd(&sRS[n1 + 8], s2);
        }
    }
    __syncthreads();

    float inv[2][2];
    #pragma unroll
    for (int fi = 0; fi < 2; ++fi) {
        int n1 = wn * 32 + fi * 16 + (lane >> 2);
        inv[fi][0] = 1.f / sRS[n1];
        inv[fi][1] = 1.f / sRS[n1 + 8];
    }
    float* sY = (float*)(smem + EP_SY);
    #pragma unroll
    for (int fi = 0; fi < 2; ++fi) {
        int n1 = wn * 32 + fi * 16 + (lane >> 2);
        #pragma unroll
        for (int bj = 0; bj < 4; ++bj) {
            int cl = wm * 32 + bj * 8 + (lane & 3) * 2;
            sY[n1 * 65 + cl]           = acco[fi][bj][0] * inv[fi][0];
            sY[n1 * 65 + cl + 1]       = acco[fi][bj][1] * inv[fi][0];
            sY[(n1 + 8) * 65 + cl]     = acco[fi][bj][2] * inv[fi][1];
            sY[(n1 + 8) * 65 + cl + 1] = acco[fi][bj][3] * inv[fi][1];
        }
    }
    float* sWm = (float*)(smem + EP_SW);
    float* sBv = (float*)(smem + EP_SB);
    for (int i = tid; i < 4096; i += 256) sWm[(i >> 6) * 65 + (i & 63)] = Ww[i];
    if (tid < 64) sBv[tid] = Wb[tid];
    __syncthreads();

    float* sZ = (float*)(smem + EP_SZ);
    {
        const int nb = (tid >> 3) * 4;
        const int cb = (tid & 7) * 8;
        ull a2[8][2];
        #pragma unroll
        for (int j = 0; j < 8; ++j) { a2[j][0] = 0ull; a2[j][1] = 0ull; }
        #pragma unroll 8
        for (int ci = 0; ci < 64; ++ci) {
            ull y01 = pk2(sY[nb * 65 + ci],       sY[(nb + 1) * 65 + ci]);
            ull y23 = pk2(sY[(nb + 2) * 65 + ci], sY[(nb + 3) * 65 + ci]);
            #pragma unroll
            for (int j = 0; j < 8; ++j) {
                float wv = sWm[(cb + j) * 65 + ci];
                ull wd = pk2(wv, wv);
                fma2(a2[j][0], wd, y01);
                fma2(a2[j][1], wd, y23);
            }
        }
        #pragma unroll
        for (int j = 0; j < 8; ++j) {
            float bv = sBv[cb + j];
            float2 v01 = upk2(a2[j][0]);
            float2 v23 = upk2(a2[j][1]);
            sZ[nb * 65 + cb + j]       = v01.x + bv;
            sZ[(nb + 1) * 65 + cb + j] = v01.y + bv;
            sZ[(nb + 2) * 65 + cb + j] = v23.x + bv;
            sZ[(nb + 3) * 65 + cb + j] = v23.y + bv;
        }
    }
    __syncthreads();

    for (int i = tid; i < 8192; i += 256) {
        int c = i >> 7, n = i & 127;
        size_t o = ((size_t)(b * CH + c) << 12) + n0 + n;
        z[o] = sZ[n * 65 + c] + x[o];
    }
}

// ---------------------------------------------------------------------------
// Launch
// ---------------------------------------------------------------------------
extern "C" void kernel_launch(void* const* d_in, const int* in_sizes, int n_in,
                              void* d_out, int out_size)
{
    const float* x       = (const float*)d_in[0];
    const float* conv1_w = (const float*)d_in[1];
    const float* bn1_g   = (const float*)d_in[2];
    const float* bn1_b   = (const float*)d_in[3];
    const float* theta_w = (const float*)d_in[4];
    const float* theta_b = (const float*)d_in[5];
    const float* phi_w   = (const float*)d_in[6];
    const float* phi_b   = (const float*)d_in[7];
    const float* gw      = (const float*)d_in[8];
    const float* gb      = (const float*)d_in[9];
    const float* W_w     = (const float*)d_in[10];
    const float* W_b     = (const float*)d_in[11];
    const float* conv2_w = (const float*)d_in[12];
    const float* bn2_g   = (const float*)d_in[13];
    const float* bn2_b   = (const float*)d_in[14];
    float* out = (float*)d_out;

    float *p_c1, *p_z, *p_mean, *p_rstd, *p_stats;
    __nv_bfloat16 *p_wm, *p_thH, *p_thL, *p_phH, *p_phL, *p_gH, *p_gL;
    cudaGetSymbolAddress((void**)&p_c1,   g_c1raw);
    cudaGetSymbolAddress((void**)&p_z,    g_z);
    cudaGetSymbolAddress((void**)&p_mean, g_mean);
    cudaGetSymbolAddress((void**)&p_rstd, g_rstd);
    cudaGetSymbolAddress((void**)&p_stats, g_stats);
    cudaGetSymbolAddress((void**)&p_wm,   g_wmma);
    cudaGetSymbolAddress((void**)&p_thH,  g_thT_hi);
    cudaGetSymbolAddress((void**)&p_thL,  g_thT_lo);
    cudaGetSymbolAddress((void**)&p_phH,  g_phT_hi);
    cudaGetSymbolAddress((void**)&p_phL,  g_phT_lo);
    cudaGetSymbolAddress((void**)&p_gH,   g_g_hi);
    cudaGetSymbolAddress((void**)&p_gL,   g_g_lo);

    cudaFuncSetAttribute(conv_mma_kernel<0>, cudaFuncAttributeMaxDynamicSharedMemorySize, CV_SMEM0);
    cudaFuncSetAttribute(conv_mma_kernel<1>, cudaFuncAttributeMaxDynamicSharedMemorySize, CV_SMEM1);
    cudaFuncSetAttribute(attn_fused_kernel,  cudaFuncAttributeMaxDynamicSharedMemorySize, FA_SMEM);

    wtrans_mma_kernel<<<720, 256>>>(conv1_w, theta_w, phi_w, gw, conv2_w, p_wm);

    // conv1 (+BN1 stats)
    cudaMemsetAsync(p_stats, 0, 2 * CH * sizeof(float));
    conv_mma_kernel<0><<<dim3(32, BATCH, 2), 256, CV_SMEM0>>>(
        x, p_wm, p_c1, p_stats,
        nullptr, nullptr, nullptr, nullptr, nullptr, nullptr, nullptr,
        nullptr, nullptr, nullptr, nullptr, nullptr, nullptr);
    bnfinalize_kernel<<<1, 64>>>(p_stats, p_mean, p_rstd);

    // fused projections (BN1 on input; direct bf16 hi/lo outputs; theta*log2e)
    conv_mma_kernel<1><<<dim3(32, BATCH, 2), 256, CV_SMEM1>>>(
        p_c1, p_wm + (size_t)9 * 2 * 4096, nullptr, nullptr,
        p_mean, p_rstd, bn1_g, bn1_b, theta_b, phi_b, gb,
        p_thH, p_thL, p_phH, p_phL, p_gH, p_gL);

    // fused attention + 1x1 W conv + residual -> z
    attn_fused_kernel<<<dim3(32, BATCH), 256, FA_SMEM>>>(
        p_thH, p_thL, p_phH, p_phL, p_gH, p_gL, W_w, W_b, x, p_z);

    // conv2 (+BN2 stats) + final BN apply
    cudaMemsetAsync(p_stats, 0, 2 * CH * sizeof(float));
    conv_mma_kernel<0><<<dim3(32, BATCH, 2), 256, CV_SMEM0>>>(
        p_z, p_wm + (size_t)4 * 9 * 2 * 4096, p_c1, p_stats,
        nullptr, nullptr, nullptr, nullptr, nullptr, nullptr, nullptr,
        nullptr, nullptr, nullptr, nullptr, nullptr, nullptr);
    bnfinalize_kernel<<<1, 64>>>(p_stats, p_mean, p_rstd);
    bnapply_kernel<<<(BATCH * CH * NPIX) / 256, 256>>>(p_c1, p_mean, p_rstd, bn2_g, bn2_b, out);
}